// round 2
// baseline (speedup 1.0000x reference)
#include <cuda_runtime.h>
#include <cuda_bf16.h>
#include <math.h>

#define N_NODES 50000
#define FEA 128
#define NBRF 64
#define NNBR 12
#define NEDGE 600000      // N_NODES * NNBR
#define COUT 256
#define IN_DIM 320

#define K2TILES 9375      // NEDGE / 64
#define GRID2 148
#define GRID4 1563        // ceil(N_NODES / 32)

// ---------------- scratch (static device allocations only) ----------------
__device__ float g_h[(size_t)N_NODES * 512];        // h1 (c<256) | h2 (c>=256), 102.4 MB
__device__ float g_g[(size_t)NEDGE * 256];          // gated pre-activation, 614.4 MB
__device__ float g_s[(size_t)N_NODES * 128];        // neighbor-summed messages
__device__ float g_part1[GRID2 * 512];              // BN1 partials: [block][sum256|sq256]
__device__ float g_part2[GRID4 * 256];              // BN2 partials: [block][sum128|sq128]
__device__ float g_bn1_scale[256], g_bn1_shift[256];
__device__ float g_bn2_scale[128], g_bn2_shift[128];
__device__ int   g_idx64;

// ---------------- math helpers (match jax.nn semantics in fp32) ----------------
__device__ __forceinline__ float sigmoidf_(float x) {
    // 1/(1+exp(-x)); __fdividef(1,inf)=0 handles the x->-inf limit
    return __fdividef(1.0f, 1.0f + __expf(-x));
}
__device__ __forceinline__ float softplusf_(float x) {
    // logaddexp(x, 0) = max(x,0) + log1p(exp(-|x|))
    float t = __expf(-fabsf(x));
    return fmaxf(x, 0.0f) + __logf(1.0f + t);
}

// ---------------- k0: detect edge_index dtype ----------------
__global__ void k0_detect(const void* __restrict__ ei) {
    if (threadIdx.x == 0) {
        // Sample 8 int64 words from the middle of row 0 (src = repeat(arange)):
        // genuine int64 values are < N_NODES; int32 data aliased as int64 packs two
        // random indices -> >= 2^32 with overwhelming probability.
        const long long* p = (const long long*)ei;
        int ok = 1;
        #pragma unroll
        for (int q = 0; q < 8; ++q) {
            long long v = p[NEDGE / 2 + q];
            if (v < 0 || v >= N_NODES) ok = 0;
        }
        g_idx64 = ok;
    }
}

// ---------------- k1: node GEMM  h[i][c0+c] = sum_k x[i][k] * W[c][woff+k] ----------------
// block: 64 rows x 256 cols, K=128. grid (782, 2). dyn smem: xs[64*128] + ws[256*130]
__global__ void __launch_bounds__(256, 1)
k1_node_gemm(const float* __restrict__ x, const float* __restrict__ W) {
    extern __shared__ float sm[];
    float* xs = sm;                 // 64*128
    float* ws = sm + 64 * 128;      // 256*130 (pad 130 -> conflict-light, float2-aligned)
    const int i0 = blockIdx.x * 64;
    const int c0 = blockIdx.y * 256;
    const int woff = (c0 == 0) ? 0 : 128;
    const int tid = threadIdx.x;

    for (int idx = tid; idx < 256 * 128; idx += 256) {
        int c = idx >> 7, k = idx & 127;
        ws[c * 130 + k] = W[c * IN_DIM + woff + k];
    }
    for (int idx = tid; idx < 64 * 128; idx += 256) {
        int i = i0 + (idx >> 7);
        xs[idx] = (i < N_NODES) ? x[(size_t)i0 * 128 + idx] : 0.0f;
    }
    __syncthreads();

    const int lane = tid & 31, wrp = tid >> 5;
    float acc[8][8];
    #pragma unroll
    for (int m = 0; m < 8; ++m)
        #pragma unroll
        for (int j = 0; j < 8; ++j) acc[m][j] = 0.0f;

    #pragma unroll 4
    for (int k = 0; k < 128; k += 2) {
        float2 a[8], w[8];
        #pragma unroll
        for (int m = 0; m < 8; ++m)
            a[m] = *(const float2*)&xs[(wrp * 8 + m) * 128 + k];   // broadcast in warp
        #pragma unroll
        for (int j = 0; j < 8; ++j)
            w[j] = *(const float2*)&ws[(lane + 32 * j) * 130 + k]; // ~2-way conflict
        #pragma unroll
        for (int m = 0; m < 8; ++m)
            #pragma unroll
            for (int j = 0; j < 8; ++j) {
                acc[m][j] += a[m].x * w[j].x;
                acc[m][j] += a[m].y * w[j].y;
            }
    }

    #pragma unroll
    for (int m = 0; m < 8; ++m) {
        int i = i0 + wrp * 8 + m;
        if (i < N_NODES) {
            #pragma unroll
            for (int j = 0; j < 8; ++j)
                g_h[(size_t)i * 512 + c0 + lane + 32 * j] = acc[m][j];
        }
    }
}

// ---------------- k2: edge GEMM + gather + bias + BN1 partial stats ----------------
// persistent grid of 148 blocks; tile = 64 edges x 256 channels, K=64
// smem: ws[256*66] | eas[64*68] | bs[256] | nbs[64]
__global__ void __launch_bounds__(256, 1)
k2_edge(const float* __restrict__ ea, const void* __restrict__ ei,
        const float* __restrict__ W, const float* __restrict__ b) {
    extern __shared__ float sm[];
    float* ws  = sm;                     // 16896
    float* eas = ws + 256 * 66;          // 4352
    float* bs  = eas + 64 * 68;          // 256
    int*   nbs = (int*)(bs + 256);       // 64

    const int tid = threadIdx.x, lane = tid & 31, wrp = tid >> 5;

    for (int idx = tid; idx < 256 * 64; idx += 256) {
        int c = idx >> 6, k = idx & 63;
        ws[c * 66 + k] = W[c * IN_DIM + 256 + k];
    }
    bs[tid] = b[tid];
    const int use64 = g_idx64;

    float ssum[8], ssq[8];
    #pragma unroll
    for (int j = 0; j < 8; ++j) { ssum[j] = 0.0f; ssq[j] = 0.0f; }

    for (int tile = blockIdx.x; tile < K2TILES; tile += gridDim.x) {
        const int e0 = tile * 64;
        __syncthreads();  // protect eas/nbs reuse
        {
            const float4* src = (const float4*)(ea + (size_t)e0 * 64);
            for (int i4 = tid; i4 < 1024; i4 += 256) {
                int e = i4 >> 4;
                int kk = (i4 & 15) << 2;
                *(float4*)&eas[e * 68 + kk] = src[i4];
            }
        }
        if (tid < 64) {
            long long nv = use64 ? ((const long long*)ei)[NEDGE + e0 + tid]
                                 : (long long)((const int*)ei)[NEDGE + e0 + tid];
            nbs[tid] = (int)nv;
        }
        __syncthreads();

        float acc[8][8];
        #pragma unroll
        for (int m = 0; m < 8; ++m)
            #pragma unroll
            for (int j = 0; j < 8; ++j) acc[m][j] = 0.0f;

        #pragma unroll 4
        for (int k = 0; k < 64; k += 2) {
            float2 a[8], w[8];
            #pragma unroll
            for (int m = 0; m < 8; ++m)
                a[m] = *(const float2*)&eas[(wrp * 8 + m) * 68 + k];   // broadcast
            #pragma unroll
            for (int j = 0; j < 8; ++j)
                w[j] = *(const float2*)&ws[(lane + 32 * j) * 66 + k];  // ~2-way
            #pragma unroll
            for (int m = 0; m < 8; ++m)
                #pragma unroll
                for (int j = 0; j < 8; ++j) {
                    acc[m][j] += a[m].x * w[j].x;
                    acc[m][j] += a[m].y * w[j].y;
                }
        }

        // epilogue: + h1[nbr] + h2[src] + b, write g, accumulate BN1 stats
        #pragma unroll
        for (int m = 0; m < 8; ++m) {
            const int el = wrp * 8 + m;
            const int e  = e0 + el;
            const size_t hb1 = (size_t)nbs[el] * 512;
            const size_t hb2 = (size_t)(e / 12) * 512 + 256;
            const size_t gb  = (size_t)e * 256;
            #pragma unroll
            for (int j = 0; j < 8; ++j) {
                int c = lane + 32 * j;
                float gv = acc[m][j] + g_h[hb1 + c] + g_h[hb2 + c] + bs[c];
                g_g[gb + c] = gv;
                ssum[j] += gv;
                ssq[j]  += gv * gv;
            }
        }
    }

    // deterministic per-block reduction of BN1 partials (reuse eas as [8][256])
    __syncthreads();
    float* red = eas;
    #pragma unroll
    for (int j = 0; j < 8; ++j) red[wrp * 256 + lane + 32 * j] = ssum[j];
    __syncthreads();
    if (tid < 256) {
        float t = 0.0f;
        #pragma unroll
        for (int w = 0; w < 8; ++w) t += red[w * 256 + tid];
        g_part1[blockIdx.x * 512 + tid] = t;
    }
    __syncthreads();
    #pragma unroll
    for (int j = 0; j < 8; ++j) red[wrp * 256 + lane + 32 * j] = ssq[j];
    __syncthreads();
    if (tid < 256) {
        float t = 0.0f;
        #pragma unroll
        for (int w = 0; w < 8; ++w) t += red[w * 256 + tid];
        g_part1[blockIdx.x * 512 + 256 + tid] = t;
    }
}

// ---------------- k3: BN1 finalize ----------------
__global__ void k3_bn1(const float* __restrict__ g1, const float* __restrict__ b1) {
    __shared__ float tots[512];
    int tid = threadIdx.x;
    if (tid < 512) {
        float t = 0.0f;
        for (int bb = 0; bb < GRID2; ++bb) t += g_part1[bb * 512 + tid];
        tots[tid] = t;
    }
    __syncthreads();
    if (tid < 256) {
        float mean = tots[tid] * (1.0f / (float)NEDGE);
        float var  = tots[256 + tid] * (1.0f / (float)NEDGE) - mean * mean;
        float rstd = rsqrtf(var + 1e-5f);
        float sc = g1[tid] * rstd;
        g_bn1_scale[tid] = sc;
        g_bn1_shift[tid] = b1[tid] - mean * sc;
    }
}

// ---------------- k4: per-node 12-edge reduce + activations + BN2 partials ----------------
// block = 8 warps, each warp handles 4 nodes (lane -> channel lane+32j)
__global__ void __launch_bounds__(256)
k4_reduce() {
    __shared__ float red[8 * 128];
    const int tid = threadIdx.x, lane = tid & 31, wrp = tid >> 5;

    float scf[4], shf[4], scc[4], shc[4];
    #pragma unroll
    for (int j = 0; j < 4; ++j) {
        int c = lane + 32 * j;
        scf[j] = g_bn1_scale[c];       shf[j] = g_bn1_shift[c];
        scc[j] = g_bn1_scale[128 + c]; shc[j] = g_bn1_shift[128 + c];
    }
    float stm[4] = {0, 0, 0, 0}, stq[4] = {0, 0, 0, 0};
    const int base_i = blockIdx.x * 32 + wrp * 4;

    for (int nn = 0; nn < 4; ++nn) {
        int i = base_i + nn;
        if (i < N_NODES) {
            float s[4] = {0, 0, 0, 0};
            #pragma unroll
            for (int el = 0; el < 12; ++el) {
                size_t gb = ((size_t)(i * 12 + el)) * 256;
                #pragma unroll
                for (int j = 0; j < 4; ++j) {
                    int c = lane + 32 * j;
                    float gf = g_g[gb + c]       * scf[j] + shf[j];
                    float gc = g_g[gb + 128 + c] * scc[j] + shc[j];
                    s[j] += sigmoidf_(gf) * softplusf_(gc);
                }
            }
            #pragma unroll
            for (int j = 0; j < 4; ++j) {
                g_s[(size_t)i * 128 + lane + 32 * j] = s[j];
                stm[j] += s[j];
                stq[j] += s[j] * s[j];
            }
        }
    }

    #pragma unroll
    for (int j = 0; j < 4; ++j) red[wrp * 128 + lane + 32 * j] = stm[j];
    __syncthreads();
    if (tid < 128) {
        float t = 0.0f;
        #pragma unroll
        for (int w = 0; w < 8; ++w) t += red[w * 128 + tid];
        g_part2[blockIdx.x * 256 + tid] = t;
    }
    __syncthreads();
    #pragma unroll
    for (int j = 0; j < 4; ++j) red[wrp * 128 + lane + 32 * j] = stq[j];
    __syncthreads();
    if (tid < 128) {
        float t = 0.0f;
        #pragma unroll
        for (int w = 0; w < 8; ++w) t += red[w * 128 + tid];
        g_part2[blockIdx.x * 256 + 128 + tid] = t;
    }
}

// ---------------- k5: BN2 finalize (one block per channel) ----------------
__global__ void k5_bn2(const float* __restrict__ g2, const float* __restrict__ b2) {
    __shared__ float rs[256], rq[256];
    const int c = blockIdx.x, tid = threadIdx.x;
    float ps = 0.0f, pq = 0.0f;
    for (int bb = tid; bb < GRID4; bb += 256) {
        ps += g_part2[bb * 256 + c];
        pq += g_part2[bb * 256 + 128 + c];
    }
    rs[tid] = ps; rq[tid] = pq;
    __syncthreads();
    for (int off = 128; off > 0; off >>= 1) {
        if (tid < off) { rs[tid] += rs[tid + off]; rq[tid] += rq[tid + off]; }
        __syncthreads();
    }
    if (tid == 0) {
        float mean = rs[0] * (1.0f / (float)N_NODES);
        float var  = rq[0] * (1.0f / (float)N_NODES) - mean * mean;
        float rstd = rsqrtf(var + 1e-5f);
        float sc = g2[c] * rstd;
        g_bn2_scale[c] = sc;
        g_bn2_shift[c] = b2[c] - mean * sc;
    }
}

// ---------------- k6: out = softplus(x + BN2(s)) ----------------
__global__ void k6_final(const float* __restrict__ x, float* __restrict__ out) {
    const int total4 = N_NODES * 32;
    for (int i4 = blockIdx.x * blockDim.x + threadIdx.x; i4 < total4;
         i4 += gridDim.x * blockDim.x) {
        float4 xv = ((const float4*)x)[i4];
        float4 sv = ((const float4*)g_s)[i4];
        int cb = (i4 & 31) << 2;
        float4 o;
        o.x = softplusf_(xv.x + sv.x * g_bn2_scale[cb + 0] + g_bn2_shift[cb + 0]);
        o.y = softplusf_(xv.y + sv.y * g_bn2_scale[cb + 1] + g_bn2_shift[cb + 1]);
        o.z = softplusf_(xv.z + sv.z * g_bn2_scale[cb + 2] + g_bn2_shift[cb + 2]);
        o.w = softplusf_(xv.w + sv.w * g_bn2_scale[cb + 3] + g_bn2_shift[cb + 3]);
        ((float4*)out)[i4] = o;
    }
}

// ---------------- launch ----------------
extern "C" void kernel_launch(void* const* d_in, const int* in_sizes, int n_in,
                              void* d_out, int out_size) {
    const float* x   = (const float*)d_in[0];
    const void*  ei  = d_in[1];                 // int32 or int64 -> detected
    const float* ea  = (const float*)d_in[2];
    const float* W   = (const float*)d_in[3];
    const float* b   = (const float*)d_in[4];
    const float* b1g = (const float*)d_in[5];
    const float* b1b = (const float*)d_in[6];
    const float* b2g = (const float*)d_in[7];
    const float* b2b = (const float*)d_in[8];
    float* out = (float*)d_out;

    const int smem1 = (64 * 128 + 256 * 130) * 4;           // 165,888 B
    const int smem2 = (256 * 66 + 64 * 68 + 256 + 64) * 4;  //  86,272 B
    cudaFuncSetAttribute(k1_node_gemm, cudaFuncAttributeMaxDynamicSharedMemorySize, smem1);
    cudaFuncSetAttribute(k2_edge,      cudaFuncAttributeMaxDynamicSharedMemorySize, smem2);

    k0_detect<<<1, 32>>>(ei);
    k1_node_gemm<<<dim3(782, 2), 256, smem1>>>(x, W);
    k2_edge<<<GRID2, 256, smem2>>>(ea, ei, W, b);
    k3_bn1<<<1, 512>>>(b1g, b1b);
    k4_reduce<<<GRID4, 256>>>();
    k5_bn2<<<128, 256>>>(b2g, b2b);
    k6_final<<<592, 256>>>(x, out);
}

// round 4
// speedup vs baseline: 2.4902x; 2.4902x over previous
#include <cuda_runtime.h>
#include <cuda_bf16.h>
#include <math.h>
#include <stdint.h>

#define N_NODES 50000
#define NEDGE   600000
#define IN_DIM  320

#define NT1   782          // node tiles of 64 rows
#define NT2   9375         // edge tiles of 64 edges
#define GRID2 148          // persistent edge-GEMM blocks
#define GRID4 1563         // ceil(N_NODES/32)

// ---------------- scratch ----------------
__device__ float g_h[(size_t)N_NODES * 512];
__device__ float g_g[(size_t)NEDGE * 256];
__device__ float g_s[(size_t)N_NODES * 128];
__device__ float g_part1[GRID2 * 512];
__device__ float g_part2[GRID4 * 256];
__device__ float g_bn1_scale[256], g_bn1_shift[256];
__device__ float g_bn2_scale[128], g_bn2_shift[128];
__device__ int   g_idx64;

// ---------------- helpers ----------------
__device__ __forceinline__ uint32_t f2tf(float f) {
    uint32_t u;
    asm("cvt.rna.tf32.f32 %0, %1;" : "=r"(u) : "f"(f));
    return u;
}
__device__ __forceinline__ void mma_tf32(float* d, const uint32_t* a, const uint32_t* b) {
    asm volatile(
        "mma.sync.aligned.m16n8k8.row.col.f32.tf32.tf32.f32 "
        "{%0,%1,%2,%3}, {%4,%5,%6,%7}, {%8,%9}, {%0,%1,%2,%3};\n"
        : "+f"(d[0]), "+f"(d[1]), "+f"(d[2]), "+f"(d[3])
        : "r"(a[0]), "r"(a[1]), "r"(a[2]), "r"(a[3]), "r"(b[0]), "r"(b[1]));
}
__device__ __forceinline__ float sigmoidf_(float x) {
    return __fdividef(1.0f, 1.0f + __expf(-x));
}
__device__ __forceinline__ float softplusf_(float x) {
    float t = __expf(-fabsf(x));
    return fmaxf(x, 0.0f) + __logf(1.0f + t);
}

// ---------------- k0: detect edge_index dtype ----------------
__global__ void k0_detect(const void* __restrict__ ei) {
    if (threadIdx.x == 0) {
        const long long* p = (const long long*)ei;
        int ok = 1;
        #pragma unroll
        for (int q = 0; q < 8; ++q) {
            long long v = p[NEDGE / 2 + q];
            if (v < 0 || v >= N_NODES) ok = 0;
        }
        g_idx64 = ok;
    }
}

// ================= k1: node GEMM (tf32 mma.sync) =================
// tile 64 nodes x 256 out, K=128; grid (NT1, 2) y = half
// smem floats: Wt[128][264] | A[64][132]
#define K1_WT_STRIDE 264
#define K1_A_STRIDE  132
#define K1_SMEM_FL   (128 * K1_WT_STRIDE + 64 * K1_A_STRIDE)

__global__ void __launch_bounds__(256, 1)
k1_gemm(const float* __restrict__ x, const float* __restrict__ W) {
    extern __shared__ float sm[];
    float* wt = sm;                         // [k][n] tf32 bits
    float* as = sm + 128 * K1_WT_STRIDE;    // [row][k] tf32 bits
    uint32_t* wtu = (uint32_t*)wt;
    uint32_t* asu = (uint32_t*)as;

    const int tid = threadIdx.x, lane = tid & 31, w = tid >> 5;
    const int g = lane >> 2, tg = lane & 3;
    const int wr = (w >> 2) * 32, wc = (w & 3) * 64;
    const int i0 = blockIdx.x * 64;
    const int woff = blockIdx.y * 128;

    for (int idx = tid; idx < 256 * 128; idx += 256) {
        int n = idx >> 7, k = idx & 127;
        wtu[k * K1_WT_STRIDE + n] = f2tf(W[n * IN_DIM + woff + k]);
    }
    #pragma unroll
    for (int q = 0; q < 8; ++q) {
        int i4 = tid + q * 256;
        int er = i4 >> 5, kk = (i4 & 31) * 4;
        int i = i0 + er;
        float4 v = (i < N_NODES) ? ((const float4*)x)[(size_t)i * 32 + (kk >> 2)]
                                 : make_float4(0.f, 0.f, 0.f, 0.f);
        uint32_t* dst = &asu[er * K1_A_STRIDE + kk];
        dst[0] = f2tf(v.x); dst[1] = f2tf(v.y);
        dst[2] = f2tf(v.z); dst[3] = f2tf(v.w);
    }
    __syncthreads();

    float acc[2][8][4];
    #pragma unroll
    for (int mt = 0; mt < 2; ++mt)
        #pragma unroll
        for (int nt = 0; nt < 8; ++nt)
            #pragma unroll
            for (int q = 0; q < 4; ++q) acc[mt][nt][q] = 0.0f;

    #pragma unroll
    for (int ks = 0; ks < 16; ++ks) {
        const int k0 = ks * 8;
        uint32_t afr[2][4];
        #pragma unroll
        for (int mt = 0; mt < 2; ++mt) {
            int r0 = wr + mt * 16 + g;
            afr[mt][0] = asu[r0 * K1_A_STRIDE + k0 + tg];
            afr[mt][1] = asu[(r0 + 8) * K1_A_STRIDE + k0 + tg];
            afr[mt][2] = asu[r0 * K1_A_STRIDE + k0 + tg + 4];
            afr[mt][3] = asu[(r0 + 8) * K1_A_STRIDE + k0 + tg + 4];
        }
        #pragma unroll
        for (int nt = 0; nt < 8; ++nt) {
            uint32_t bfr[2];
            int c0 = wc + nt * 8 + g;
            bfr[0] = wtu[(k0 + tg) * K1_WT_STRIDE + c0];
            bfr[1] = wtu[(k0 + tg + 4) * K1_WT_STRIDE + c0];
            mma_tf32(acc[0][nt], afr[0], bfr);
            mma_tf32(acc[1][nt], afr[1], bfr);
        }
    }

    // store h
    const int hoff = blockIdx.y * 256;
    #pragma unroll
    for (int mt = 0; mt < 2; ++mt)
        #pragma unroll
        for (int rr = 0; rr < 2; ++rr) {
            int i = i0 + wr + mt * 16 + rr * 8 + g;
            if (i < N_NODES) {
                float* ho = g_h + (size_t)i * 512 + hoff;
                #pragma unroll
                for (int nt = 0; nt < 8; ++nt) {
                    int c = wc + nt * 8 + 2 * tg;
                    *(float2*)(ho + c) =
                        make_float2(acc[mt][nt][rr * 2], acc[mt][nt][rr * 2 + 1]);
                }
            }
        }
}

// ================= k2: edge GEMM + gather/bias + fused BN1 stats =================
// persistent grid 148; tile 64 edges x 256 ch, K=64
// smem floats: Wt[64][264] | A[64][68] | bias[256] | nbs[64] | sred[8][128]
#define K2_WT_STRIDE 264
#define K2_A_STRIDE  68
#define K2_WT_FL (64 * K2_WT_STRIDE)
#define K2_A_FL  (64 * K2_A_STRIDE)
#define K2_SMEM_FL (K2_WT_FL + K2_A_FL + 256 + 64 + 8 * 128)

__global__ void __launch_bounds__(256, 1)
k2_edge(const float* __restrict__ ea, const void* __restrict__ ei,
        const float* __restrict__ W, const float* __restrict__ b) {
    extern __shared__ float sm[];
    float* wt = sm;
    float* as = sm + K2_WT_FL;
    float* bs = as + K2_A_FL;
    int*  nbs = (int*)(bs + 256);
    float* sred = (float*)(nbs + 64);
    uint32_t* wtu = (uint32_t*)wt;
    uint32_t* asu = (uint32_t*)as;

    const int tid = threadIdx.x, lane = tid & 31, w = tid >> 5;
    const int g = lane >> 2, tg = lane & 3;
    const int wr = (w >> 2) * 32, wc = (w & 3) * 64;

    for (int idx = tid; idx < 256 * 64; idx += 256) {
        int n = idx >> 6, k = idx & 63;
        wtu[k * K2_WT_STRIDE + n] = f2tf(W[n * IN_DIM + 256 + k]);
    }
    bs[tid] = b[tid];
    const int use64 = g_idx64;

    float ssum[16], ssq[16];
    #pragma unroll
    for (int q = 0; q < 16; ++q) { ssum[q] = 0.0f; ssq[q] = 0.0f; }

    for (int tile = blockIdx.x; tile < NT2; tile += gridDim.x) {
        const int e0 = tile * 64;
        __syncthreads();
        {
            const float4* src4 = (const float4*)(ea + (size_t)e0 * 64);
            #pragma unroll
            for (int q = 0; q < 4; ++q) {
                int i4 = tid + q * 256;
                int er = i4 >> 4, kk = (i4 & 15) * 4;
                float4 v = src4[i4];
                uint32_t* dst = &asu[er * K2_A_STRIDE + kk];
                dst[0] = f2tf(v.x); dst[1] = f2tf(v.y);
                dst[2] = f2tf(v.z); dst[3] = f2tf(v.w);
            }
            if (tid < 64)
                nbs[tid] = use64 ? (int)((const long long*)ei)[NEDGE + e0 + tid]
                                 : ((const int*)ei)[NEDGE + e0 + tid];
        }
        __syncthreads();

        float acc[2][8][4];
        #pragma unroll
        for (int mt = 0; mt < 2; ++mt)
            #pragma unroll
            for (int nt = 0; nt < 8; ++nt)
                #pragma unroll
                for (int q = 0; q < 4; ++q) acc[mt][nt][q] = 0.0f;

        #pragma unroll
        for (int ks = 0; ks < 8; ++ks) {
            const int k0 = ks * 8;
            uint32_t afr[2][4];
            #pragma unroll
            for (int mt = 0; mt < 2; ++mt) {
                int r0 = wr + mt * 16 + g;
                afr[mt][0] = asu[r0 * K2_A_STRIDE + k0 + tg];
                afr[mt][1] = asu[(r0 + 8) * K2_A_STRIDE + k0 + tg];
                afr[mt][2] = asu[r0 * K2_A_STRIDE + k0 + tg + 4];
                afr[mt][3] = asu[(r0 + 8) * K2_A_STRIDE + k0 + tg + 4];
            }
            #pragma unroll
            for (int nt = 0; nt < 8; ++nt) {
                uint32_t bfr[2];
                int c0 = wc + nt * 8 + g;
                bfr[0] = wtu[(k0 + tg) * K2_WT_STRIDE + c0];
                bfr[1] = wtu[(k0 + tg + 4) * K2_WT_STRIDE + c0];
                mma_tf32(acc[0][nt], afr[0], bfr);
                mma_tf32(acc[1][nt], afr[1], bfr);
            }
        }

        // epilogue: + h1[nbr] + h2[src] + bias; store g; accumulate stats
        #pragma unroll
        for (int mt = 0; mt < 2; ++mt)
            #pragma unroll
            for (int rr = 0; rr < 2; ++rr) {
                const int er = wr + mt * 16 + rr * 8 + g;
                const int e = e0 + er;
                const float* h1 = g_h + (size_t)nbs[er] * 512;
                const float* h2 = g_h + (size_t)(e / 12) * 512 + 256;
                float* go = g_g + (size_t)e * 256;
                #pragma unroll
                for (int nt = 0; nt < 8; ++nt) {
                    int c = wc + nt * 8 + 2 * tg;
                    float2 p1 = *(const float2*)(h1 + c);
                    float2 p2 = *(const float2*)(h2 + c);
                    float v0 = acc[mt][nt][rr * 2]     + p1.x + p2.x + bs[c];
                    float v1 = acc[mt][nt][rr * 2 + 1] + p1.y + p2.y + bs[c + 1];
                    *(float2*)(go + c) = make_float2(v0, v1);
                    ssum[nt * 2]     += v0; ssq[nt * 2]     += v0 * v0;
                    ssum[nt * 2 + 1] += v1; ssq[nt * 2 + 1] += v1 * v1;
                }
            }
    }

    // reduce stats: lanes sharing a col set differ only in g bits -> xor 4,8,16
    #pragma unroll
    for (int q = 0; q < 16; ++q) {
        #pragma unroll
        for (int off = 4; off < 32; off <<= 1) {
            ssum[q] += __shfl_xor_sync(0xFFFFFFFFu, ssum[q], off);
            ssq[q]  += __shfl_xor_sync(0xFFFFFFFFu, ssq[q],  off);
        }
    }
    __syncthreads();
    if (lane < 4) {
        #pragma unroll
        for (int nt = 0; nt < 8; ++nt)
            #pragma unroll
            for (int j = 0; j < 2; ++j) {
                int cl = nt * 8 + 2 * lane + j;
                sred[w * 128 + cl]      = ssum[nt * 2 + j];
                sred[w * 128 + 64 + cl] = ssq[nt * 2 + j];
            }
    }
    __syncthreads();
    {
        int c = tid, strip = c >> 6, cl = c & 63;
        float s  = sred[strip * 128 + cl]      + sred[(strip + 4) * 128 + cl];
        float sq = sred[strip * 128 + 64 + cl] + sred[(strip + 4) * 128 + 64 + cl];
        g_part1[blockIdx.x * 512 + c]       = s;
        g_part1[blockIdx.x * 512 + 256 + c] = sq;
    }
}

// ---------------- k3: BN1 finalize ----------------
__global__ void k3_bn1(const float* __restrict__ g1, const float* __restrict__ b1) {
    __shared__ float tots[512];
    int tid = threadIdx.x;
    if (tid < 512) {
        float t = 0.0f;
        for (int bb = 0; bb < GRID2; ++bb) t += g_part1[bb * 512 + tid];
        tots[tid] = t;
    }
    __syncthreads();
    if (tid < 256) {
        float mean = tots[tid] * (1.0f / (float)NEDGE);
        float var  = tots[256 + tid] * (1.0f / (float)NEDGE) - mean * mean;
        float rstd = rsqrtf(var + 1e-5f);
        float sc = g1[tid] * rstd;
        g_bn1_scale[tid] = sc;
        g_bn1_shift[tid] = b1[tid] - mean * sc;
    }
}

// ---------------- k4: per-node reduce + activations + BN2 partials ----------------
__global__ void __launch_bounds__(256)
k4_reduce() {
    __shared__ float red[8 * 128];
    const int tid = threadIdx.x, lane = tid & 31, wrp = tid >> 5;

    float scf[4], shf[4], scc[4], shc[4];
    #pragma unroll
    for (int j = 0; j < 4; ++j) {
        int c = lane + 32 * j;
        scf[j] = g_bn1_scale[c];       shf[j] = g_bn1_shift[c];
        scc[j] = g_bn1_scale[128 + c]; shc[j] = g_bn1_shift[128 + c];
    }
    float stm[4] = {0, 0, 0, 0}, stq[4] = {0, 0, 0, 0};
    const int base_i = blockIdx.x * 32 + wrp * 4;

    for (int nn = 0; nn < 4; ++nn) {
        int i = base_i + nn;
        if (i < N_NODES) {
            float s[4] = {0, 0, 0, 0};
            #pragma unroll
            for (int el = 0; el < 12; ++el) {
                size_t gb = ((size_t)(i * 12 + el)) * 256;
                #pragma unroll
                for (int j = 0; j < 4; ++j) {
                    int c = lane + 32 * j;
                    float gf = g_g[gb + c]       * scf[j] + shf[j];
                    float gc = g_g[gb + 128 + c] * scc[j] + shc[j];
                    s[j] += sigmoidf_(gf) * softplusf_(gc);
                }
            }
            #pragma unroll
            for (int j = 0; j < 4; ++j) {
                g_s[(size_t)i * 128 + lane + 32 * j] = s[j];
                stm[j] += s[j];
                stq[j] += s[j] * s[j];
            }
        }
    }

    #pragma unroll
    for (int j = 0; j < 4; ++j) red[wrp * 128 + lane + 32 * j] = stm[j];
    __syncthreads();
    if (tid < 128) {
        float t = 0.0f;
        #pragma unroll
        for (int w = 0; w < 8; ++w) t += red[w * 128 + tid];
        g_part2[blockIdx.x * 256 + tid] = t;
    }
    __syncthreads();
    #pragma unroll
    for (int j = 0; j < 4; ++j) red[wrp * 128 + lane + 32 * j] = stq[j];
    __syncthreads();
    if (tid < 128) {
        float t = 0.0f;
        #pragma unroll
        for (int w = 0; w < 8; ++w) t += red[w * 128 + tid];
        g_part2[blockIdx.x * 256 + 128 + tid] = t;
    }
}

// ---------------- k5: BN2 finalize ----------------
__global__ void k5_bn2(const float* __restrict__ g2, const float* __restrict__ b2) {
    __shared__ float rs[256], rq[256];
    const int c = blockIdx.x, tid = threadIdx.x;
    float ps = 0.0f, pq = 0.0f;
    for (int bb = tid; bb < GRID4; bb += 256) {
        ps += g_part2[bb * 256 + c];
        pq += g_part2[bb * 256 + 128 + c];
    }
    rs[tid] = ps; rq[tid] = pq;
    __syncthreads();
    for (int off = 128; off > 0; off >>= 1) {
        if (tid < off) { rs[tid] += rs[tid + off]; rq[tid] += rq[tid + off]; }
        __syncthreads();
    }
    if (tid == 0) {
        float mean = rs[0] * (1.0f / (float)N_NODES);
        float var  = rq[0] * (1.0f / (float)N_NODES) - mean * mean;
        float rstd = rsqrtf(var + 1e-5f);
        float sc = g2[c] * rstd;
        g_bn2_scale[c] = sc;
        g_bn2_shift[c] = b2[c] - mean * sc;
    }
}

// ---------------- k6: out = softplus(x + BN2(s)) ----------------
__global__ void k6_final(const float* __restrict__ x, float* __restrict__ out) {
    const int total4 = N_NODES * 32;
    for (int i4 = blockIdx.x * blockDim.x + threadIdx.x; i4 < total4;
         i4 += gridDim.x * blockDim.x) {
        float4 xv = ((const float4*)x)[i4];
        float4 sv = ((const float4*)g_s)[i4];
        int cb = (i4 & 31) << 2;
        float4 o;
        o.x = softplusf_(xv.x + sv.x * g_bn2_scale[cb + 0] + g_bn2_shift[cb + 0]);
        o.y = softplusf_(xv.y + sv.y * g_bn2_scale[cb + 1] + g_bn2_shift[cb + 1]);
        o.z = softplusf_(xv.z + sv.z * g_bn2_scale[cb + 2] + g_bn2_shift[cb + 2]);
        o.w = softplusf_(xv.w + sv.w * g_bn2_scale[cb + 3] + g_bn2_shift[cb + 3]);
        ((float4*)out)[i4] = o;
    }
}

// ---------------- launch ----------------
extern "C" void kernel_launch(void* const* d_in, const int* in_sizes, int n_in,
                              void* d_out, int out_size) {
    const float* x   = (const float*)d_in[0];
    const void*  ei  = d_in[1];
    const float* ea  = (const float*)d_in[2];
    const float* W   = (const float*)d_in[3];
    const float* b   = (const float*)d_in[4];
    const float* b1g = (const float*)d_in[5];
    const float* b1b = (const float*)d_in[6];
    const float* b2g = (const float*)d_in[7];
    const float* b2b = (const float*)d_in[8];
    float* out = (float*)d_out;

    const int smem1 = K1_SMEM_FL * 4;   // 168,960 B
    const int smem2 = K2_SMEM_FL * 4;   //  90,368 B
    cudaFuncSetAttribute(k1_gemm, cudaFuncAttributeMaxDynamicSharedMemorySize, smem1);
    cudaFuncSetAttribute(k2_edge, cudaFuncAttributeMaxDynamicSharedMemorySize, smem2);

    k0_detect<<<1, 32>>>(ei);
    k1_gemm<<<dim3(NT1, 2), 256, smem1>>>(x, W);
    k2_edge<<<GRID2, 256, smem2>>>(ea, ei, W, b);
    k3_bn1<<<1, 512>>>(b1g, b1b);
    k4_reduce<<<GRID4, 256>>>();
    k5_bn2<<<128, 256>>>(b2g, b2b);
    k6_final<<<592, 256>>>(x, out);
}

// round 5
// speedup vs baseline: 3.3485x; 1.3447x over previous
#include <cuda_runtime.h>
#include <cuda_fp16.h>
#include <math.h>
#include <stdint.h>

#define N_NODES 50000
#define NEDGE   600000
#define IN_DIM  320

#define NT1   782          // node tiles of 64 rows
#define NT2   9375         // edge tiles of 64 edges (9375*64 == NEDGE exactly)
#define GRID2 148          // persistent edge-GEMM blocks
#define GRID4 1563         // ceil(N_NODES/32)

// ---------------- scratch ----------------
__device__ __half g_h[(size_t)N_NODES * 512];    // 51.2 MB -> L2-resident
__device__ __half g_g[(size_t)NEDGE * 256];      // 307.2 MB
__device__ float  g_s[(size_t)N_NODES * 128];
__device__ float  g_part1[GRID2 * 512];
__device__ float  g_part2[GRID4 * 256];
__device__ float  g_bn1_scale[256], g_bn1_shift[256];
__device__ float  g_bn2_scale[128], g_bn2_shift[128];
__device__ int    g_idx64;

// ---------------- helpers ----------------
__device__ __forceinline__ uint32_t f2tf(float f) {
    uint32_t u;
    asm("cvt.rna.tf32.f32 %0, %1;" : "=r"(u) : "f"(f));
    return u;
}
__device__ __forceinline__ void mma_tf32(float* d, const uint32_t* a, const uint32_t* b) {
    asm volatile(
        "mma.sync.aligned.m16n8k8.row.col.f32.tf32.tf32.f32 "
        "{%0,%1,%2,%3}, {%4,%5,%6,%7}, {%8,%9}, {%0,%1,%2,%3};\n"
        : "+f"(d[0]), "+f"(d[1]), "+f"(d[2]), "+f"(d[3])
        : "r"(a[0]), "r"(a[1]), "r"(a[2]), "r"(a[3]), "r"(b[0]), "r"(b[1]));
}
__device__ __forceinline__ float sigmoidf_(float x) {
    return __fdividef(1.0f, 1.0f + __expf(-x));
}
__device__ __forceinline__ float softplusf_(float x) {
    float t = __expf(-fabsf(x));
    return fmaxf(x, 0.0f) + __logf(1.0f + t);
}

// ---------------- k0: detect edge_index dtype ----------------
__global__ void k0_detect(const void* __restrict__ ei) {
    if (threadIdx.x == 0) {
        const long long* p = (const long long*)ei;
        int ok = 1;
        #pragma unroll
        for (int q = 0; q < 8; ++q) {
            long long v = p[NEDGE / 2 + q];
            if (v < 0 || v >= N_NODES) ok = 0;
        }
        g_idx64 = ok;
    }
}

// ================= k1: node GEMM (tf32 mma.sync), h stored fp16 =================
// tile 64 nodes x 256 out, K=128; grid (NT1, 2) y = half
#define K1_WT_STRIDE 264
#define K1_A_STRIDE  132
#define K1_SMEM_FL   (128 * K1_WT_STRIDE + 64 * K1_A_STRIDE)

__global__ void __launch_bounds__(256, 1)
k1_gemm(const float* __restrict__ x, const float* __restrict__ W) {
    extern __shared__ float sm[];
    uint32_t* wtu = (uint32_t*)sm;                       // [k][n]
    uint32_t* asu = (uint32_t*)(sm + 128 * K1_WT_STRIDE); // [row][k]

    const int tid = threadIdx.x, lane = tid & 31, w = tid >> 5;
    const int g = lane >> 2, tg = lane & 3;
    const int wr = (w >> 2) * 32, wc = (w & 3) * 64;
    const int i0 = blockIdx.x * 64;
    const int woff = blockIdx.y * 128;

    for (int idx = tid; idx < 256 * 128; idx += 256) {
        int n = idx >> 7, k = idx & 127;
        wtu[k * K1_WT_STRIDE + n] = f2tf(W[n * IN_DIM + woff + k]);
    }
    #pragma unroll
    for (int q = 0; q < 8; ++q) {
        int i4 = tid + q * 256;
        int er = i4 >> 5, kk = (i4 & 31) * 4;
        int i = i0 + er;
        float4 v = (i < N_NODES) ? ((const float4*)x)[(size_t)i * 32 + (kk >> 2)]
                                 : make_float4(0.f, 0.f, 0.f, 0.f);
        uint32_t* dst = &asu[er * K1_A_STRIDE + kk];
        dst[0] = f2tf(v.x); dst[1] = f2tf(v.y);
        dst[2] = f2tf(v.z); dst[3] = f2tf(v.w);
    }
    __syncthreads();

    float acc[2][8][4];
    #pragma unroll
    for (int mt = 0; mt < 2; ++mt)
        #pragma unroll
        for (int nt = 0; nt < 8; ++nt)
            #pragma unroll
            for (int q = 0; q < 4; ++q) acc[mt][nt][q] = 0.0f;

    #pragma unroll
    for (int ks = 0; ks < 16; ++ks) {
        const int k0 = ks * 8;
        uint32_t afr[2][4];
        #pragma unroll
        for (int mt = 0; mt < 2; ++mt) {
            int r0 = wr + mt * 16 + g;
            afr[mt][0] = asu[r0 * K1_A_STRIDE + k0 + tg];
            afr[mt][1] = asu[(r0 + 8) * K1_A_STRIDE + k0 + tg];
            afr[mt][2] = asu[r0 * K1_A_STRIDE + k0 + tg + 4];
            afr[mt][3] = asu[(r0 + 8) * K1_A_STRIDE + k0 + tg + 4];
        }
        #pragma unroll
        for (int nt = 0; nt < 8; ++nt) {
            uint32_t bfr[2];
            int c0 = wc + nt * 8 + g;
            bfr[0] = wtu[(k0 + tg) * K1_WT_STRIDE + c0];
            bfr[1] = wtu[(k0 + tg + 4) * K1_WT_STRIDE + c0];
            mma_tf32(acc[0][nt], afr[0], bfr);
            mma_tf32(acc[1][nt], afr[1], bfr);
        }
    }

    const int hoff = blockIdx.y * 256;
    #pragma unroll
    for (int mt = 0; mt < 2; ++mt)
        #pragma unroll
        for (int rr = 0; rr < 2; ++rr) {
            int i = i0 + wr + mt * 16 + rr * 8 + g;
            if (i < N_NODES) {
                __half* ho = g_h + (size_t)i * 512 + hoff;
                #pragma unroll
                for (int nt = 0; nt < 8; ++nt) {
                    int c = wc + nt * 8 + 2 * tg;
                    *(__half2*)(ho + c) =
                        __floats2half2_rn(acc[mt][nt][rr * 2], acc[mt][nt][rr * 2 + 1]);
                }
            }
        }
}

// ================= k2: edge GEMM + fp16 gather/bias + fused BN1 stats =================
// persistent grid 148; tile 64 edges x 256 ch, K=64; ea prefetched into regs
#define K2_WT_STRIDE 264
#define K2_A_STRIDE  68
#define K2_WT_FL (64 * K2_WT_STRIDE)
#define K2_A_FL  (64 * K2_A_STRIDE)
#define K2_SMEM_FL (K2_WT_FL + K2_A_FL + 256 + 64 + 8 * 128)

__global__ void __launch_bounds__(256, 1)
k2_edge(const float* __restrict__ ea, const void* __restrict__ ei,
        const float* __restrict__ W, const float* __restrict__ b) {
    extern __shared__ float sm[];
    uint32_t* wtu = (uint32_t*)sm;
    uint32_t* asu = (uint32_t*)(sm + K2_WT_FL);
    float* bs = sm + K2_WT_FL + K2_A_FL;
    int*  nbs = (int*)(bs + 256);
    float* sred = (float*)(nbs + 64);

    const int tid = threadIdx.x, lane = tid & 31, w = tid >> 5;
    const int g = lane >> 2, tg = lane & 3;
    const int wr = (w >> 2) * 32, wc = (w & 3) * 64;

    for (int idx = tid; idx < 256 * 64; idx += 256) {
        int n = idx >> 6, k = idx & 63;
        wtu[k * K2_WT_STRIDE + n] = f2tf(W[n * IN_DIM + 256 + k]);
    }
    bs[tid] = b[tid];
    const int use64 = g_idx64;

    float ssum[16], ssq[16];
    #pragma unroll
    for (int q = 0; q < 16; ++q) { ssum[q] = 0.0f; ssq[q] = 0.0f; }

    // ---- prefetch tile 0 into registers ----
    float4 pv[4];
    int pnb = 0;
    int tile = blockIdx.x;
    {
        const float4* src4 = (const float4*)(ea + (size_t)tile * 64 * 64);
        #pragma unroll
        for (int q = 0; q < 4; ++q) pv[q] = src4[tid + q * 256];
        if (tid < 64)
            pnb = use64 ? (int)((const long long*)ei)[NEDGE + tile * 64 + tid]
                        : ((const int*)ei)[NEDGE + tile * 64 + tid];
    }

    for (; tile < NT2; tile += GRID2) {
        const int e0 = tile * 64;
        __syncthreads();   // prior tile's mma reads of asu done
        #pragma unroll
        for (int q = 0; q < 4; ++q) {
            int i4 = tid + q * 256;
            int er = i4 >> 4, kk = (i4 & 15) * 4;
            uint32_t* dst = &asu[er * K2_A_STRIDE + kk];
            dst[0] = f2tf(pv[q].x); dst[1] = f2tf(pv[q].y);
            dst[2] = f2tf(pv[q].z); dst[3] = f2tf(pv[q].w);
        }
        if (tid < 64) nbs[tid] = pnb;
        __syncthreads();

        float acc[2][8][4];
        #pragma unroll
        for (int mt = 0; mt < 2; ++mt)
            #pragma unroll
            for (int nt = 0; nt < 8; ++nt)
                #pragma unroll
                for (int q = 0; q < 4; ++q) acc[mt][nt][q] = 0.0f;

        #pragma unroll
        for (int ks = 0; ks < 8; ++ks) {
            const int k0 = ks * 8;
            uint32_t afr[2][4];
            #pragma unroll
            for (int mt = 0; mt < 2; ++mt) {
                int r0 = wr + mt * 16 + g;
                afr[mt][0] = asu[r0 * K2_A_STRIDE + k0 + tg];
                afr[mt][1] = asu[(r0 + 8) * K2_A_STRIDE + k0 + tg];
                afr[mt][2] = asu[r0 * K2_A_STRIDE + k0 + tg + 4];
                afr[mt][3] = asu[(r0 + 8) * K2_A_STRIDE + k0 + tg + 4];
            }
            #pragma unroll
            for (int nt = 0; nt < 8; ++nt) {
                uint32_t bfr[2];
                int c0 = wc + nt * 8 + g;
                bfr[0] = wtu[(k0 + tg) * K2_WT_STRIDE + c0];
                bfr[1] = wtu[(k0 + tg + 4) * K2_WT_STRIDE + c0];
                mma_tf32(acc[0][nt], afr[0], bfr);
                mma_tf32(acc[1][nt], afr[1], bfr);
            }
        }

        // ---- prefetch next tile (overlaps epilogue gathers) ----
        if (tile + GRID2 < NT2) {
            const float4* src4 = (const float4*)(ea + (size_t)(tile + GRID2) * 64 * 64);
            #pragma unroll
            for (int q = 0; q < 4; ++q) pv[q] = src4[tid + q * 256];
            if (tid < 64)
                pnb = use64 ? (int)((const long long*)ei)[NEDGE + (tile + GRID2) * 64 + tid]
                            : ((const int*)ei)[NEDGE + (tile + GRID2) * 64 + tid];
        }

        // epilogue: + h1[nbr] + h2[src] + bias; store g (fp16); accumulate stats
        #pragma unroll
        for (int mt = 0; mt < 2; ++mt)
            #pragma unroll
            for (int rr = 0; rr < 2; ++rr) {
                const int er = wr + mt * 16 + rr * 8 + g;
                const int e = e0 + er;
                const __half* h1 = g_h + (size_t)nbs[er] * 512;
                const __half* h2 = g_h + (size_t)(e / 12) * 512 + 256;
                __half* go = g_g + (size_t)e * 256;
                #pragma unroll
                for (int nt = 0; nt < 8; ++nt) {
                    int c = wc + nt * 8 + 2 * tg;
                    float2 p1 = __half22float2(*(const __half2*)(h1 + c));
                    float2 p2 = __half22float2(*(const __half2*)(h2 + c));
                    float v0 = acc[mt][nt][rr * 2]     + p1.x + p2.x + bs[c];
                    float v1 = acc[mt][nt][rr * 2 + 1] + p1.y + p2.y + bs[c + 1];
                    *(__half2*)(go + c) = __floats2half2_rn(v0, v1);
                    ssum[nt * 2]     += v0; ssq[nt * 2]     += v0 * v0;
                    ssum[nt * 2 + 1] += v1; ssq[nt * 2 + 1] += v1 * v1;
                }
            }
    }

    // reduce stats across lanes sharing the same columns (xor 4,8,16)
    #pragma unroll
    for (int q = 0; q < 16; ++q) {
        #pragma unroll
        for (int off = 4; off < 32; off <<= 1) {
            ssum[q] += __shfl_xor_sync(0xFFFFFFFFu, ssum[q], off);
            ssq[q]  += __shfl_xor_sync(0xFFFFFFFFu, ssq[q],  off);
        }
    }
    __syncthreads();
    if (lane < 4) {
        #pragma unroll
        for (int nt = 0; nt < 8; ++nt)
            #pragma unroll
            for (int j = 0; j < 2; ++j) {
                int cl = nt * 8 + 2 * lane + j;
                sred[w * 128 + cl]      = ssum[nt * 2 + j];
                sred[w * 128 + 64 + cl] = ssq[nt * 2 + j];
            }
    }
    __syncthreads();
    {
        int c = tid, strip = c >> 6, cl = c & 63;
        float s  = sred[strip * 128 + cl]      + sred[(strip + 4) * 128 + cl];
        float sq = sred[strip * 128 + 64 + cl] + sred[(strip + 4) * 128 + 64 + cl];
        g_part1[blockIdx.x * 512 + c]       = s;
        g_part1[blockIdx.x * 512 + 256 + c] = sq;
    }
}

// ---------------- k3: BN1 finalize ----------------
__global__ void k3_bn1(const float* __restrict__ g1, const float* __restrict__ b1) {
    __shared__ float tots[512];
    int tid = threadIdx.x;
    if (tid < 512) {
        float t = 0.0f;
        for (int bb = 0; bb < GRID2; ++bb) t += g_part1[bb * 512 + tid];
        tots[tid] = t;
    }
    __syncthreads();
    if (tid < 256) {
        float mean = tots[tid] * (1.0f / (float)NEDGE);
        float var  = tots[256 + tid] * (1.0f / (float)NEDGE) - mean * mean;
        float rstd = rsqrtf(var + 1e-5f);
        float sc = g1[tid] * rstd;
        g_bn1_scale[tid] = sc;
        g_bn1_shift[tid] = b1[tid] - mean * sc;
    }
}

// ---------------- k4: per-node reduce + activations + BN2 partials (fp16 g) ----------------
__global__ void __launch_bounds__(256)
k4_reduce() {
    __shared__ float red[8 * 128];
    const int tid = threadIdx.x, lane = tid & 31, wrp = tid >> 5;

    float scf[2][2], shf[2][2], scc[2][2], shc[2][2];
    #pragma unroll
    for (int j = 0; j < 2; ++j)
        #pragma unroll
        for (int q = 0; q < 2; ++q) {
            int c = 2 * lane + 64 * j + q;
            scf[j][q] = g_bn1_scale[c];       shf[j][q] = g_bn1_shift[c];
            scc[j][q] = g_bn1_scale[128 + c]; shc[j][q] = g_bn1_shift[128 + c];
        }
    float stm[2][2] = {{0, 0}, {0, 0}}, stq[2][2] = {{0, 0}, {0, 0}};
    const int base_i = blockIdx.x * 32 + wrp * 4;

    for (int nn = 0; nn < 4; ++nn) {
        int i = base_i + nn;
        if (i < N_NODES) {
            float s[2][2] = {{0, 0}, {0, 0}};
            const __half* grow = g_g + (size_t)i * 12 * 256;
            #pragma unroll
            for (int el = 0; el < 12; ++el) {
                #pragma unroll
                for (int j = 0; j < 2; ++j) {
                    int c = 2 * lane + 64 * j;
                    float2 gf = __half22float2(*(const __half2*)(grow + el * 256 + c));
                    float2 gc = __half22float2(*(const __half2*)(grow + el * 256 + 128 + c));
                    float f0 = gf.x * scf[j][0] + shf[j][0];
                    float f1 = gf.y * scf[j][1] + shf[j][1];
                    float c0 = gc.x * scc[j][0] + shc[j][0];
                    float c1 = gc.y * scc[j][1] + shc[j][1];
                    s[j][0] += sigmoidf_(f0) * softplusf_(c0);
                    s[j][1] += sigmoidf_(f1) * softplusf_(c1);
                }
            }
            #pragma unroll
            for (int j = 0; j < 2; ++j) {
                *(float2*)(g_s + (size_t)i * 128 + 2 * lane + 64 * j) =
                    make_float2(s[j][0], s[j][1]);
                stm[j][0] += s[j][0]; stq[j][0] += s[j][0] * s[j][0];
                stm[j][1] += s[j][1]; stq[j][1] += s[j][1] * s[j][1];
            }
        }
    }

    #pragma unroll
    for (int j = 0; j < 2; ++j)
        #pragma unroll
        for (int q = 0; q < 2; ++q)
            red[wrp * 128 + 2 * lane + 64 * j + q] = stm[j][q];
    __syncthreads();
    if (tid < 128) {
        float t = 0.0f;
        #pragma unroll
        for (int w = 0; w < 8; ++w) t += red[w * 128 + tid];
        g_part2[blockIdx.x * 256 + tid] = t;
    }
    __syncthreads();
    #pragma unroll
    for (int j = 0; j < 2; ++j)
        #pragma unroll
        for (int q = 0; q < 2; ++q)
            red[wrp * 128 + 2 * lane + 64 * j + q] = stq[j][q];
    __syncthreads();
    if (tid < 128) {
        float t = 0.0f;
        #pragma unroll
        for (int w = 0; w < 8; ++w) t += red[w * 128 + tid];
        g_part2[blockIdx.x * 256 + 128 + tid] = t;
    }
}

// ---------------- k5: BN2 finalize ----------------
__global__ void k5_bn2(const float* __restrict__ g2, const float* __restrict__ b2) {
    __shared__ float rs[256], rq[256];
    const int c = blockIdx.x, tid = threadIdx.x;
    float ps = 0.0f, pq = 0.0f;
    for (int bb = tid; bb < GRID4; bb += 256) {
        ps += g_part2[bb * 256 + c];
        pq += g_part2[bb * 256 + 128 + c];
    }
    rs[tid] = ps; rq[tid] = pq;
    __syncthreads();
    for (int off = 128; off > 0; off >>= 1) {
        if (tid < off) { rs[tid] += rs[tid + off]; rq[tid] += rq[tid + off]; }
        __syncthreads();
    }
    if (tid == 0) {
        float mean = rs[0] * (1.0f / (float)N_NODES);
        float var  = rq[0] * (1.0f / (float)N_NODES) - mean * mean;
        float rstd = rsqrtf(var + 1e-5f);
        float sc = g2[c] * rstd;
        g_bn2_scale[c] = sc;
        g_bn2_shift[c] = b2[c] - mean * sc;
    }
}

// ---------------- k6: out = softplus(x + BN2(s)) ----------------
__global__ void k6_final(const float* __restrict__ x, float* __restrict__ out) {
    const int total4 = N_NODES * 32;
    for (int i4 = blockIdx.x * blockDim.x + threadIdx.x; i4 < total4;
         i4 += gridDim.x * blockDim.x) {
        float4 xv = ((const float4*)x)[i4];
        float4 sv = ((const float4*)g_s)[i4];
        int cb = (i4 & 31) << 2;
        float4 o;
        o.x = softplusf_(xv.x + sv.x * g_bn2_scale[cb + 0] + g_bn2_shift[cb + 0]);
        o.y = softplusf_(xv.y + sv.y * g_bn2_scale[cb + 1] + g_bn2_shift[cb + 1]);
        o.z = softplusf_(xv.z + sv.z * g_bn2_scale[cb + 2] + g_bn2_shift[cb + 2]);
        o.w = softplusf_(xv.w + sv.w * g_bn2_scale[cb + 3] + g_bn2_shift[cb + 3]);
        ((float4*)out)[i4] = o;
    }
}

// ---------------- launch ----------------
extern "C" void kernel_launch(void* const* d_in, const int* in_sizes, int n_in,
                              void* d_out, int out_size) {
    const float* x   = (const float*)d_in[0];
    const void*  ei  = d_in[1];
    const float* ea  = (const float*)d_in[2];
    const float* W   = (const float*)d_in[3];
    const float* b   = (const float*)d_in[4];
    const float* b1g = (const float*)d_in[5];
    const float* b1b = (const float*)d_in[6];
    const float* b2g = (const float*)d_in[7];
    const float* b2b = (const float*)d_in[8];
    float* out = (float*)d_out;

    const int smem1 = K1_SMEM_FL * 4;
    const int smem2 = K2_SMEM_FL * 4;
    cudaFuncSetAttribute(k1_gemm, cudaFuncAttributeMaxDynamicSharedMemorySize, smem1);
    cudaFuncSetAttribute(k2_edge, cudaFuncAttributeMaxDynamicSharedMemorySize, smem2);

    k0_detect<<<1, 32>>>(ei);
    k1_gemm<<<dim3(NT1, 2), 256, smem1>>>(x, W);
    k2_edge<<<GRID2, 256, smem2>>>(ea, ei, W, b);
    k3_bn1<<<1, 512>>>(b1g, b1b);
    k4_reduce<<<GRID4, 256>>>();
    k5_bn2<<<128, 256>>>(b2g, b2b);
    k6_final<<<592, 256>>>(x, out);
}

// round 7
// speedup vs baseline: 4.3920x; 1.3116x over previous
#include <cuda_runtime.h>
#include <cuda_fp16.h>
#include <math.h>
#include <stdint.h>

#define N_NODES 50000
#define NEDGE   600000
#define IN_DIM  320

#define NT1   782          // node tiles of 64 rows
#define NT2   9375         // edge tiles of 64 edges (9375*64 == NEDGE)
#define GRID2P 148         // k2 tile-pair strides (grid = 296)
#define GRID4 1563         // ceil(N_NODES/32)

// ---------------- scratch ----------------
__device__ __half g_h[(size_t)N_NODES * 512];    // 51.2 MB -> L2-resident
__device__ __half g_g[(size_t)NEDGE * 256];      // 307.2 MB
__device__ float  g_s[(size_t)N_NODES * 128];
__device__ float  g_part1[2 * GRID2P * 256];     // [pair][half][sum128|sq128]
__device__ float  g_part2[GRID4 * 256];
__device__ float  g_bn1_scale[256], g_bn1_shift[256];
__device__ float  g_bn2_scale[128], g_bn2_shift[128];
__device__ int    g_idx64;

// ---------------- helpers ----------------
__device__ __forceinline__ uint32_t f2tf(float f) {
    uint32_t u;
    asm("cvt.rna.tf32.f32 %0, %1;" : "=r"(u) : "f"(f));
    return u;
}
__device__ __forceinline__ void mma_tf32(float* d, const uint32_t* a, const uint32_t* b) {
    asm volatile(
        "mma.sync.aligned.m16n8k8.row.col.f32.tf32.tf32.f32 "
        "{%0,%1,%2,%3}, {%4,%5,%6,%7}, {%8,%9}, {%0,%1,%2,%3};\n"
        : "+f"(d[0]), "+f"(d[1]), "+f"(d[2]), "+f"(d[3])
        : "r"(a[0]), "r"(a[1]), "r"(a[2]), "r"(a[3]), "r"(b[0]), "r"(b[1]));
}
__device__ __forceinline__ float sigmoidf_(float x) {
    return __fdividef(1.0f, 1.0f + __expf(-x));
}
__device__ __forceinline__ float softplusf_(float x) {
    float t = __expf(-fabsf(x));
    return fmaxf(x, 0.0f) + __logf(1.0f + t);
}

// ---------------- k0: detect edge_index dtype ----------------
__global__ void k0_detect(const void* __restrict__ ei) {
    if (threadIdx.x == 0) {
        const long long* p = (const long long*)ei;
        int ok = 1;
        #pragma unroll
        for (int q = 0; q < 8; ++q) {
            long long v = p[NEDGE / 2 + q];
            if (v < 0 || v >= N_NODES) ok = 0;
        }
        g_idx64 = ok;
    }
}

// ================= k1: node GEMM (tf32 mma.sync), h stored fp16 =================
#define K1_WT_STRIDE 264
#define K1_A_STRIDE  132
#define K1_SMEM_FL   (128 * K1_WT_STRIDE + 64 * K1_A_STRIDE)

__global__ void __launch_bounds__(256, 1)
k1_gemm(const float* __restrict__ x, const float* __restrict__ W) {
    extern __shared__ float sm[];
    uint32_t* wtu = (uint32_t*)sm;                        // [k][n]
    uint32_t* asu = (uint32_t*)(sm + 128 * K1_WT_STRIDE); // [row][k]

    const int tid = threadIdx.x, lane = tid & 31, w = tid >> 5;
    const int g = lane >> 2, tg = lane & 3;
    const int wr = (w >> 2) * 32, wc = (w & 3) * 64;
    const int i0 = blockIdx.x * 64;
    const int woff = blockIdx.y * 128;

    for (int idx = tid; idx < 256 * 128; idx += 256) {
        int n = idx >> 7, k = idx & 127;
        wtu[k * K1_WT_STRIDE + n] = f2tf(W[n * IN_DIM + woff + k]);
    }
    #pragma unroll
    for (int q = 0; q < 8; ++q) {
        int i4 = tid + q * 256;
        int er = i4 >> 5, kk = (i4 & 31) * 4;
        int i = i0 + er;
        float4 v = (i < N_NODES) ? ((const float4*)x)[(size_t)i * 32 + (kk >> 2)]
                                 : make_float4(0.f, 0.f, 0.f, 0.f);
        uint32_t* dst = &asu[er * K1_A_STRIDE + kk];
        dst[0] = f2tf(v.x); dst[1] = f2tf(v.y);
        dst[2] = f2tf(v.z); dst[3] = f2tf(v.w);
    }
    __syncthreads();

    float acc[2][8][4];
    #pragma unroll
    for (int mt = 0; mt < 2; ++mt)
        #pragma unroll
        for (int nt = 0; nt < 8; ++nt)
            #pragma unroll
            for (int q = 0; q < 4; ++q) acc[mt][nt][q] = 0.0f;

    #pragma unroll
    for (int ks = 0; ks < 16; ++ks) {
        const int k0 = ks * 8;
        uint32_t afr[2][4];
        #pragma unroll
        for (int mt = 0; mt < 2; ++mt) {
            int r0 = wr + mt * 16 + g;
            afr[mt][0] = asu[r0 * K1_A_STRIDE + k0 + tg];
            afr[mt][1] = asu[(r0 + 8) * K1_A_STRIDE + k0 + tg];
            afr[mt][2] = asu[r0 * K1_A_STRIDE + k0 + tg + 4];
            afr[mt][3] = asu[(r0 + 8) * K1_A_STRIDE + k0 + tg + 4];
        }
        #pragma unroll
        for (int nt = 0; nt < 8; ++nt) {
            uint32_t bfr[2];
            int c0 = wc + nt * 8 + g;
            bfr[0] = wtu[(k0 + tg) * K1_WT_STRIDE + c0];
            bfr[1] = wtu[(k0 + tg + 4) * K1_WT_STRIDE + c0];
            mma_tf32(acc[0][nt], afr[0], bfr);
            mma_tf32(acc[1][nt], afr[1], bfr);
        }
    }

    const int hoff = blockIdx.y * 256;
    #pragma unroll
    for (int mt = 0; mt < 2; ++mt)
        #pragma unroll
        for (int rr = 0; rr < 2; ++rr) {
            int i = i0 + wr + mt * 16 + rr * 8 + g;
            if (i < N_NODES) {
                __half* ho = g_h + (size_t)i * 512 + hoff;
                #pragma unroll
                for (int nt = 0; nt < 8; ++nt) {
                    int c = wc + nt * 8 + 2 * tg;
                    *(__half2*)(ho + c) =
                        __floats2half2_rn(acc[mt][nt][rr * 2], acc[mt][nt][rr * 2 + 1]);
                }
            }
        }
}

// ================= k2: edge GEMM half-tile (128 ch) + gather + fused BN1 stats =================
// grid 296 = 148 pairs x 2 halves; 2 CTAs/SM (54 KB smem, 16 warps/SM)
#define K2_WT_STRIDE 136
#define K2_A_STRIDE  68
#define K2_WT_FL (64 * K2_WT_STRIDE)   // 8704 floats
#define K2_A_FL  (64 * K2_A_STRIDE)    // 4352 floats
#define K2_SMEM_FL (K2_WT_FL + K2_A_FL + 128 + 64 + 8 * 64)  // 13760 floats

__global__ void __launch_bounds__(256, 2)
k2_edge(const float* __restrict__ ea, const void* __restrict__ ei,
        const float* __restrict__ W, const float* __restrict__ b) {
    extern __shared__ float sm[];
    uint32_t* wtu = (uint32_t*)sm;                 // [k][n] n 0..127
    uint32_t* asu = (uint32_t*)(sm + K2_WT_FL);    // [edge][k]
    float* bs = sm + K2_WT_FL + K2_A_FL;           // 128
    int*  nbs = (int*)(bs + 128);                  // 64
    float* sred = (float*)(nbs + 64);              // 8*64

    const int tid = threadIdx.x, lane = tid & 31, w = tid >> 5;
    const int g = lane >> 2, tg = lane & 3;
    const int wr = (w >> 2) * 32, wc = (w & 3) * 32;
    const int pair = blockIdx.x >> 1, half = blockIdx.x & 1;
    const int chb = half * 128;                    // global channel base

    for (int idx = tid; idx < 128 * 64; idx += 256) {
        int n = idx >> 6, k = idx & 63;
        wtu[k * K2_WT_STRIDE + n] = f2tf(W[(chb + n) * IN_DIM + 256 + k]);
    }
    if (tid < 128) bs[tid] = b[chb + tid];
    const int use64 = g_idx64;

    float ssum[8], ssq[8];
    #pragma unroll
    for (int q = 0; q < 8; ++q) { ssum[q] = 0.0f; ssq[q] = 0.0f; }

    // ---- prefetch first tile ----
    float4 pv[4];
    int pnb = 0;
    int tile = pair;
    {
        const float4* src4 = (const float4*)(ea + (size_t)tile * 64 * 64);
        #pragma unroll
        for (int q = 0; q < 4; ++q) pv[q] = src4[tid + q * 256];
        if (tid < 64)
            pnb = use64 ? (int)((const long long*)ei)[NEDGE + tile * 64 + tid]
                        : ((const int*)ei)[NEDGE + tile * 64 + tid];
    }

    for (; tile < NT2; tile += GRID2P) {
        const int e0 = tile * 64;
        __syncthreads();
        #pragma unroll
        for (int q = 0; q < 4; ++q) {
            int i4 = tid + q * 256;
            int er = i4 >> 4, kk = (i4 & 15) * 4;
            uint32_t* dst = &asu[er * K2_A_STRIDE + kk];
            dst[0] = f2tf(pv[q].x); dst[1] = f2tf(pv[q].y);
            dst[2] = f2tf(pv[q].z); dst[3] = f2tf(pv[q].w);
        }
        if (tid < 64) nbs[tid] = pnb;
        __syncthreads();

        float acc[2][4][4];
        #pragma unroll
        for (int mt = 0; mt < 2; ++mt)
            #pragma unroll
            for (int nt = 0; nt < 4; ++nt)
                #pragma unroll
                for (int q = 0; q < 4; ++q) acc[mt][nt][q] = 0.0f;

        #pragma unroll
        for (int ks = 0; ks < 8; ++ks) {
            const int k0 = ks * 8;
            uint32_t afr[2][4];
            #pragma unroll
            for (int mt = 0; mt < 2; ++mt) {
                int r0 = wr + mt * 16 + g;
                afr[mt][0] = asu[r0 * K2_A_STRIDE + k0 + tg];
                afr[mt][1] = asu[(r0 + 8) * K2_A_STRIDE + k0 + tg];
                afr[mt][2] = asu[r0 * K2_A_STRIDE + k0 + tg + 4];
                afr[mt][3] = asu[(r0 + 8) * K2_A_STRIDE + k0 + tg + 4];
            }
            #pragma unroll
            for (int nt = 0; nt < 4; ++nt) {
                uint32_t bfr[2];
                int c0 = wc + nt * 8 + g;
                bfr[0] = wtu[(k0 + tg) * K2_WT_STRIDE + c0];
                bfr[1] = wtu[(k0 + tg + 4) * K2_WT_STRIDE + c0];
                mma_tf32(acc[0][nt], afr[0], bfr);
                mma_tf32(acc[1][nt], afr[1], bfr);
            }
        }

        // ---- prefetch next tile (overlaps epilogue gathers) ----
        if (tile + GRID2P < NT2) {
            const float4* src4 = (const float4*)(ea + (size_t)(tile + GRID2P) * 64 * 64);
            #pragma unroll
            for (int q = 0; q < 4; ++q) pv[q] = src4[tid + q * 256];
            if (tid < 64)
                pnb = use64 ? (int)((const long long*)ei)[NEDGE + (tile + GRID2P) * 64 + tid]
                            : ((const int*)ei)[NEDGE + (tile + GRID2P) * 64 + tid];
        }

        // epilogue: + h1[nbr] + h2[src] + bias; store g (fp16); accumulate stats
        #pragma unroll
        for (int mt = 0; mt < 2; ++mt)
            #pragma unroll
            for (int rr = 0; rr < 2; ++rr) {
                const int er = wr + mt * 16 + rr * 8 + g;
                const int e = e0 + er;
                const __half* h1 = g_h + (size_t)nbs[er] * 512 + chb;
                const __half* h2 = g_h + (size_t)(e / 12) * 512 + 256 + chb;
                __half* go = g_g + (size_t)e * 256 + chb;
                #pragma unroll
                for (int nt = 0; nt < 4; ++nt) {
                    int c = wc + nt * 8 + 2 * tg;
                    float2 p1 = __half22float2(*(const __half2*)(h1 + c));
                    float2 p2 = __half22float2(*(const __half2*)(h2 + c));
                    float v0 = acc[mt][nt][rr * 2]     + p1.x + p2.x + bs[c];
                    float v1 = acc[mt][nt][rr * 2 + 1] + p1.y + p2.y + bs[c + 1];
                    *(__half2*)(go + c) = __floats2half2_rn(v0, v1);
                    ssum[nt * 2]     += v0; ssq[nt * 2]     += v0 * v0;
                    ssum[nt * 2 + 1] += v1; ssq[nt * 2 + 1] += v1 * v1;
                }
            }
    }

    // reduce stats across lanes sharing the same columns (xor over g bits)
    #pragma unroll
    for (int q = 0; q < 8; ++q) {
        #pragma unroll
        for (int off = 4; off < 32; off <<= 1) {
            ssum[q] += __shfl_xor_sync(0xFFFFFFFFu, ssum[q], off);
            ssq[q]  += __shfl_xor_sync(0xFFFFFFFFu, ssq[q],  off);
        }
    }
    __syncthreads();
    if (lane < 4) {
        #pragma unroll
        for (int nt = 0; nt < 4; ++nt)
            #pragma unroll
            for (int j = 0; j < 2; ++j) {
                int sl = nt * 8 + 2 * lane + j;       // 0..31 within warp strip
                sred[w * 64 + sl]      = ssum[nt * 2 + j];
                sred[w * 64 + 32 + sl] = ssq[nt * 2 + j];
            }
    }
    __syncthreads();
    if (tid < 128) {
        int c = tid, strip = c >> 5, cl = c & 31;
        float s  = sred[strip * 64 + cl]      + sred[(strip + 4) * 64 + cl];
        float sq = sred[strip * 64 + 32 + cl] + sred[(strip + 4) * 64 + 32 + cl];
        float* dst = g_part1 + (size_t)(pair * 2 + half) * 256;
        dst[c] = s;
        dst[128 + c] = sq;
    }
}

// ---------------- k3: BN1 finalize ----------------
__global__ void k3_bn1(const float* __restrict__ g1, const float* __restrict__ b1) {
    int c = threadIdx.x;            // 0..255
    int half = c >> 7, cl = c & 127;
    float s = 0.0f, q = 0.0f;
    for (int pr = 0; pr < GRID2P; ++pr) {
        const float* src = g_part1 + (size_t)(pr * 2 + half) * 256;
        s += src[cl];
        q += src[128 + cl];
    }
    float mean = s * (1.0f / (float)NEDGE);
    float var  = q * (1.0f / (float)NEDGE) - mean * mean;
    float rstd = rsqrtf(var + 1e-5f);
    float sc = g1[c] * rstd;
    g_bn1_scale[c] = sc;
    g_bn1_shift[c] = b1[c] - mean * sc;
}

// ---------------- k4: per-node reduce + activations + BN2 partials ----------------
__global__ void __launch_bounds__(256)
k4_reduce() {
    __shared__ float red[8 * 128];
    const int tid = threadIdx.x, lane = tid & 31, wrp = tid >> 5;

    float scf[2][2], shf[2][2], scc[2][2], shc[2][2];
    #pragma unroll
    for (int j = 0; j < 2; ++j)
        #pragma unroll
        for (int q = 0; q < 2; ++q) {
            int c = 2 * lane + 64 * j + q;
            scf[j][q] = g_bn1_scale[c];       shf[j][q] = g_bn1_shift[c];
            scc[j][q] = g_bn1_scale[128 + c]; shc[j][q] = g_bn1_shift[128 + c];
        }
    float stm[2][2] = {{0, 0}, {0, 0}}, stq[2][2] = {{0, 0}, {0, 0}};
    const int base_i = blockIdx.x * 32 + wrp * 4;

    for (int nn = 0; nn < 4; ++nn) {
        int i = base_i + nn;
        if (i < N_NODES) {
            float s[2][2] = {{0, 0}, {0, 0}};
            const __half* grow = g_g + (size_t)i * 12 * 256;
            #pragma unroll
            for (int el = 0; el < 12; ++el) {
                #pragma unroll
                for (int j = 0; j < 2; ++j) {
                    int c = 2 * lane + 64 * j;
                    float2 gf = __half22float2(*(const __half2*)(grow + el * 256 + c));
                    float2 gc = __half22float2(*(const __half2*)(grow + el * 256 + 128 + c));
                    float f0 = gf.x * scf[j][0] + shf[j][0];
                    float f1 = gf.y * scf[j][1] + shf[j][1];
                    float c0 = gc.x * scc[j][0] + shc[j][0];
                    float c1 = gc.y * scc[j][1] + shc[j][1];
                    s[j][0] += sigmoidf_(f0) * softplusf_(c0);
                    s[j][1] += sigmoidf_(f1) * softplusf_(c1);
                }
            }
            #pragma unroll
            for (int j = 0; j < 2; ++j) {
                *(float2*)(g_s + (size_t)i * 128 + 2 * lane + 64 * j) =
                    make_float2(s[j][0], s[j][1]);
                stm[j][0] += s[j][0]; stq[j][0] += s[j][0] * s[j][0];
                stm[j][1] += s[j][1]; stq[j][1] += s[j][1] * s[j][1];
            }
        }
    }

    #pragma unroll
    for (int j = 0; j < 2; ++j)
        #pragma unroll
        for (int q = 0; q < 2; ++q)
            red[wrp * 128 + 2 * lane + 64 * j + q] = stm[j][q];
    __syncthreads();
    if (tid < 128) {
        float t = 0.0f;
        #pragma unroll
        for (int w = 0; w < 8; ++w) t += red[w * 128 + tid];
        g_part2[blockIdx.x * 256 + tid] = t;
    }
    __syncthreads();
    #pragma unroll
    for (int j = 0; j < 2; ++j)
        #pragma unroll
        for (int q = 0; q < 2; ++q)
            red[wrp * 128 + 2 * lane + 64 * j + q] = stq[j][q];
    __syncthreads();
    if (tid < 128) {
        float t = 0.0f;
        #pragma unroll
        for (int w = 0; w < 8; ++w) t += red[w * 128 + tid];
        g_part2[blockIdx.x * 256 + 128 + tid] = t;
    }
}

// ---------------- k5: BN2 finalize ----------------
__global__ void k5_bn2(const float* __restrict__ g2, const float* __restrict__ b2) {
    __shared__ float rs[256], rq[256];
    const int c = blockIdx.x, tid = threadIdx.x;
    float ps = 0.0f, pq = 0.0f;
    for (int bb = tid; bb < GRID4; bb += 256) {
        ps += g_part2[bb * 256 + c];
        pq += g_part2[bb * 256 + 128 + c];
    }
    rs[tid] = ps; rq[tid] = pq;
    __syncthreads();
    for (int off = 128; off > 0; off >>= 1) {
        if (tid < off) { rs[tid] += rs[tid + off]; rq[tid] += rq[tid + off]; }
        __syncthreads();
    }
    if (tid == 0) {
        float mean = rs[0] * (1.0f / (float)N_NODES);
        float var  = rq[0] * (1.0f / (float)N_NODES) - mean * mean;
        float rstd = rsqrtf(var + 1e-5f);
        float sc = g2[c] * rstd;
        g_bn2_scale[c] = sc;
        g_bn2_shift[c] = b2[c] - mean * sc;
    }
}

// ---------------- k6: out = softplus(x + BN2(s)) ----------------
__global__ void k6_final(const float* __restrict__ x, float* __restrict__ out) {
    const int total4 = N_NODES * 32;
    for (int i4 = blockIdx.x * blockDim.x + threadIdx.x; i4 < total4;
         i4 += gridDim.x * blockDim.x) {
        float4 xv = ((const float4*)x)[i4];
        float4 sv = ((const float4*)g_s)[i4];
        int cb = (i4 & 31) << 2;
        float4 o;
        o.x = softplusf_(xv.x + sv.x * g_bn2_scale[cb + 0] + g_bn2_shift[cb + 0]);
        o.y = softplusf_(xv.y + sv.y * g_bn2_scale[cb + 1] + g_bn2_shift[cb + 1]);
        o.z = softplusf_(xv.z + sv.z * g_bn2_scale[cb + 2] + g_bn2_shift[cb + 2]);
        o.w = softplusf_(xv.w + sv.w * g_bn2_scale[cb + 3] + g_bn2_shift[cb + 3]);
        ((float4*)out)[i4] = o;
    }
}

// ---------------- launch ----------------
extern "C" void kernel_launch(void* const* d_in, const int* in_sizes, int n_in,
                              void* d_out, int out_size) {
    const float* x   = (const float*)d_in[0];
    const void*  ei  = d_in[1];
    const float* ea  = (const float*)d_in[2];
    const float* W   = (const float*)d_in[3];
    const float* b   = (const float*)d_in[4];
    const float* b1g = (const float*)d_in[5];
    const float* b1b = (const float*)d_in[6];
    const float* b2g = (const float*)d_in[7];
    const float* b2b = (const float*)d_in[8];
    float* out = (float*)d_out;

    const int smem1 = K1_SMEM_FL * 4;
    const int smem2 = K2_SMEM_FL * 4;   // 55,040 B
    cudaFuncSetAttribute(k1_gemm, cudaFuncAttributeMaxDynamicSharedMemorySize, smem1);
    cudaFuncSetAttribute(k2_edge, cudaFuncAttributeMaxDynamicSharedMemorySize, smem2);

    k0_detect<<<1, 32>>>(ei);
    k1_gemm<<<dim3(NT1, 2), 256, smem1>>>(x, W);
    k2_edge<<<2 * GRID2P, 256, smem2>>>(ea, ei, W, b);
    k3_bn1<<<1, 256>>>(b1g, b1b);
    k4_reduce<<<GRID4, 256>>>();
    k5_bn2<<<128, 256>>>(b2g, b2b);
    k6_final<<<592, 256>>>(x, out);
}

// round 8
// speedup vs baseline: 4.7873x; 1.0900x over previous
#include <cuda_runtime.h>
#include <cuda_fp16.h>
#include <math.h>
#include <stdint.h>

#define N_NODES 50000
#define NEDGE   600000
#define IN_DIM  320

#define NT1   782          // node tiles of 64 rows
#define NT2   9375         // edge tiles of 64 edges (9375*64 == NEDGE)
#define GRID2P 148         // k2 tile-pair strides (grid = 296)
#define GRID4 1563         // ceil(N_NODES/32)

// ---------------- scratch ----------------
__device__ __half g_h[(size_t)N_NODES * 512];    // 51.2 MB -> L2-resident
__device__ __half g_g[(size_t)NEDGE * 256];      // 307.2 MB
__device__ float  g_s[(size_t)N_NODES * 128];
__device__ float  g_part1[2 * GRID2P * 256];     // [pair*2+half][sum128|sq128]
__device__ float  g_part2[GRID4 * 256];
__device__ float  g_bn1_scale[256], g_bn1_shift[256];
__device__ float  g_bn2_scale[128], g_bn2_shift[128];
__device__ int    g_idx64;

// ---------------- helpers ----------------
__device__ __forceinline__ uint32_t f2tf(float f) {
    uint32_t u;
    asm("cvt.rna.tf32.f32 %0, %1;" : "=r"(u) : "f"(f));
    return u;
}
__device__ __forceinline__ uint32_t smem_u32(const void* p) {
    uint32_t a;
    asm("{ .reg .u64 t; cvta.to.shared.u64 t, %1; cvt.u32.u64 %0, t; }" : "=r"(a) : "l"(p));
    return a;
}
#define LDSM_X4(r, addr) \
    asm volatile("ldmatrix.sync.aligned.m8n8.x4.shared.b16 {%0,%1,%2,%3}, [%4];" \
        : "=r"((r)[0]), "=r"((r)[1]), "=r"((r)[2]), "=r"((r)[3]) : "r"(addr))

__device__ __forceinline__ void mma_tf32(float* d, const uint32_t* a, const uint32_t* b) {
    asm volatile(
        "mma.sync.aligned.m16n8k8.row.col.f32.tf32.tf32.f32 "
        "{%0,%1,%2,%3}, {%4,%5,%6,%7}, {%8,%9}, {%0,%1,%2,%3};\n"
        : "+f"(d[0]), "+f"(d[1]), "+f"(d[2]), "+f"(d[3])
        : "r"(a[0]), "r"(a[1]), "r"(a[2]), "r"(a[3]), "r"(b[0]), "r"(b[1]));
}
__device__ __forceinline__ float sigmoidf_(float x) {
    return __fdividef(1.0f, 1.0f + __expf(-x));
}
__device__ __forceinline__ float softplusf_(float x) {
    float t = __expf(-fabsf(x));
    return fmaxf(x, 0.0f) + __logf(1.0f + t);
}

// ---------------- k0: detect edge_index dtype ----------------
__global__ void k0_detect(const void* __restrict__ ei) {
    if (threadIdx.x == 0) {
        const long long* p = (const long long*)ei;
        int ok = 1;
        #pragma unroll
        for (int q = 0; q < 8; ++q) {
            long long v = p[NEDGE / 2 + q];
            if (v < 0 || v >= N_NODES) ok = 0;
        }
        g_idx64 = ok;
    }
}

// ================= k1: node GEMM (tf32 mma.sync + LDSM), h fp16 =================
// tile 64 nodes x 128 out, K=128; grid (NT1, 2 input-halves, 2 N-halves); 2 CTAs/SM
#define K1_W_STRIDE 132
#define K1_A_STRIDE 132
#define K1_W_FL (128 * K1_W_STRIDE)    // 16896 floats
#define K1_A_FL (64 * K1_A_STRIDE)     //  8448 floats
#define K1_SMEM_FL (K1_W_FL + K1_A_FL) // 25344 floats = 101376 B

__global__ void __launch_bounds__(256, 2)
k1_gemm(const float* __restrict__ x, const float* __restrict__ W) {
    extern __shared__ float sm[];
    uint32_t* wtu = (uint32_t*)sm;             // [n 0..127][k 0..127]
    uint32_t* asu = wtu + K1_W_FL;             // [row 0..63][k 0..127]

    const int tid = threadIdx.x, lane = tid & 31, w = tid >> 5;
    const int g = lane >> 2, tg = lane & 3;
    const int wr = (w >> 2) * 32, wc = (w & 3) * 32;
    const int i0 = blockIdx.x * 64;
    const int woff = blockIdx.y * 128;         // input-feature half
    const int zn = blockIdx.z * 128;           // output-channel half

    for (int idx = tid; idx < 128 * 128; idx += 256) {
        int n = idx >> 7, k = idx & 127;
        wtu[n * K1_W_STRIDE + k] = f2tf(W[(zn + n) * IN_DIM + woff + k]);
    }
    #pragma unroll
    for (int q = 0; q < 8; ++q) {
        int i4 = tid + q * 256;
        int er = i4 >> 5, kk = (i4 & 31) * 4;
        int i = i0 + er;
        float4 v = (i < N_NODES) ? ((const float4*)x)[(size_t)i * 32 + (kk >> 2)]
                                 : make_float4(0.f, 0.f, 0.f, 0.f);
        uint32_t* dst = &asu[er * K1_A_STRIDE + kk];
        dst[0] = f2tf(v.x); dst[1] = f2tf(v.y);
        dst[2] = f2tf(v.z); dst[3] = f2tf(v.w);
    }
    __syncthreads();

    const uint32_t sA = smem_u32(asu), sW = smem_u32(wtu);
    const uint32_t aAddr0 = sA + (((wr + (lane & 15)) * K1_A_STRIDE + ((lane >> 4) << 2)) << 2);
    const uint32_t aAddr1 = aAddr0 + 16 * K1_A_STRIDE * 4;
    const uint32_t bAddr0 = sW + (((wc + (lane & 7) + ((lane >> 4) << 3)) * K1_W_STRIDE
                                   + (((lane >> 3) & 1) << 2)) << 2);
    const uint32_t bAddr1 = bAddr0 + 16 * K1_W_STRIDE * 4;

    float acc[2][4][4];
    #pragma unroll
    for (int mt = 0; mt < 2; ++mt)
        #pragma unroll
        for (int nt = 0; nt < 4; ++nt)
            #pragma unroll
            for (int q = 0; q < 4; ++q) acc[mt][nt][q] = 0.0f;

    #pragma unroll
    for (int ks = 0; ks < 16; ++ks) {
        const uint32_t off = ks * 32;          // 8 k * 4 B
        uint32_t A0[4], A1[4], B0[4], B1[4];
        LDSM_X4(A0, aAddr0 + off);
        LDSM_X4(A1, aAddr1 + off);
        LDSM_X4(B0, bAddr0 + off);
        LDSM_X4(B1, bAddr1 + off);
        mma_tf32(acc[0][0], A0, B0);     mma_tf32(acc[1][0], A1, B0);
        mma_tf32(acc[0][1], A0, B0 + 2); mma_tf32(acc[1][1], A1, B0 + 2);
        mma_tf32(acc[0][2], A0, B1);     mma_tf32(acc[1][2], A1, B1);
        mma_tf32(acc[0][3], A0, B1 + 2); mma_tf32(acc[1][3], A1, B1 + 2);
    }

    const int hoff = blockIdx.y * 256 + zn;
    #pragma unroll
    for (int mt = 0; mt < 2; ++mt)
        #pragma unroll
        for (int rr = 0; rr < 2; ++rr) {
            int i = i0 + wr + mt * 16 + rr * 8 + g;
            if (i < N_NODES) {
                __half* ho = g_h + (size_t)i * 512 + hoff;
                #pragma unroll
                for (int nt = 0; nt < 4; ++nt) {
                    int c = wc + nt * 8 + 2 * tg;
                    *(__half2*)(ho + c) =
                        __floats2half2_rn(acc[mt][nt][rr * 2], acc[mt][nt][rr * 2 + 1]);
                }
            }
        }
}

// ================= k2: edge GEMM half-tile + LDSM + gather + fused BN1 stats =================
// grid 296 = 148 pairs x 2 halves; 2 CTAs/SM
#define K2_W_STRIDE 68
#define K2_A_STRIDE 68
#define K2_W_FL (128 * K2_W_STRIDE)    // 8704 floats ([n][k])
#define K2_A_FL (64 * K2_A_STRIDE)     // 4352 floats
#define K2_SMEM_FL (K2_W_FL + K2_A_FL + 128 + 64 + 8 * 64)

__global__ void __launch_bounds__(256, 2)
k2_edge(const float* __restrict__ ea, const void* __restrict__ ei,
        const float* __restrict__ W, const float* __restrict__ b) {
    extern __shared__ float sm[];
    uint32_t* wtu = (uint32_t*)sm;                 // [n 0..127][k 0..63]
    uint32_t* asu = (uint32_t*)(sm + K2_W_FL);     // [edge][k]
    float* bs = sm + K2_W_FL + K2_A_FL;            // 128
    int*  nbs = (int*)(bs + 128);                  // 64
    float* sred = (float*)(nbs + 64);              // 8*64

    const int tid = threadIdx.x, lane = tid & 31, w = tid >> 5;
    const int g = lane >> 2, tg = lane & 3;
    const int wr = (w >> 2) * 32, wc = (w & 3) * 32;
    const int pair = blockIdx.x >> 1, half = blockIdx.x & 1;
    const int chb = half * 128;

    for (int idx = tid; idx < 128 * 64; idx += 256) {
        int n = idx >> 6, k = idx & 63;
        wtu[n * K2_W_STRIDE + k] = f2tf(W[(chb + n) * IN_DIM + 256 + k]);
    }
    if (tid < 128) bs[tid] = b[chb + tid];
    const int use64 = g_idx64;

    const uint32_t sA = smem_u32(asu), sW = smem_u32(wtu);
    const uint32_t aAddr0 = sA + (((wr + (lane & 15)) * K2_A_STRIDE + ((lane >> 4) << 2)) << 2);
    const uint32_t aAddr1 = aAddr0 + 16 * K2_A_STRIDE * 4;
    const uint32_t bAddr0 = sW + (((wc + (lane & 7) + ((lane >> 4) << 3)) * K2_W_STRIDE
                                   + (((lane >> 3) & 1) << 2)) << 2);
    const uint32_t bAddr1 = bAddr0 + 16 * K2_W_STRIDE * 4;

    float ssum[8], ssq[8];
    #pragma unroll
    for (int q = 0; q < 8; ++q) { ssum[q] = 0.0f; ssq[q] = 0.0f; }

    // ---- prefetch first tile ----
    float4 pv[4];
    int pnb = 0;
    int tile = pair;
    {
        const float4* src4 = (const float4*)(ea + (size_t)tile * 64 * 64);
        #pragma unroll
        for (int q = 0; q < 4; ++q) pv[q] = src4[tid + q * 256];
        if (tid < 64)
            pnb = use64 ? (int)((const long long*)ei)[NEDGE + tile * 64 + tid]
                        : ((const int*)ei)[NEDGE + tile * 64 + tid];
    }

    for (; tile < NT2; tile += GRID2P) {
        const int e0 = tile * 64;
        __syncthreads();
        #pragma unroll
        for (int q = 0; q < 4; ++q) {
            int i4 = tid + q * 256;
            int er = i4 >> 4, kk = (i4 & 15) * 4;
            uint32_t* dst = &asu[er * K2_A_STRIDE + kk];
            dst[0] = f2tf(pv[q].x); dst[1] = f2tf(pv[q].y);
            dst[2] = f2tf(pv[q].z); dst[3] = f2tf(pv[q].w);
        }
        if (tid < 64) nbs[tid] = pnb;
        __syncthreads();

        float acc[2][4][4];
        #pragma unroll
        for (int mt = 0; mt < 2; ++mt)
            #pragma unroll
            for (int nt = 0; nt < 4; ++nt)
                #pragma unroll
                for (int q = 0; q < 4; ++q) acc[mt][nt][q] = 0.0f;

        #pragma unroll
        for (int ks = 0; ks < 8; ++ks) {
            const uint32_t off = ks * 32;
            uint32_t A0[4], A1[4], B0[4], B1[4];
            LDSM_X4(A0, aAddr0 + off);
            LDSM_X4(A1, aAddr1 + off);
            LDSM_X4(B0, bAddr0 + off);
            LDSM_X4(B1, bAddr1 + off);
            mma_tf32(acc[0][0], A0, B0);     mma_tf32(acc[1][0], A1, B0);
            mma_tf32(acc[0][1], A0, B0 + 2); mma_tf32(acc[1][1], A1, B0 + 2);
            mma_tf32(acc[0][2], A0, B1);     mma_tf32(acc[1][2], A1, B1);
            mma_tf32(acc[0][3], A0, B1 + 2); mma_tf32(acc[1][3], A1, B1 + 2);
        }

        // ---- prefetch next tile (overlaps epilogue gathers) ----
        if (tile + GRID2P < NT2) {
            const float4* src4 = (const float4*)(ea + (size_t)(tile + GRID2P) * 64 * 64);
            #pragma unroll
            for (int q = 0; q < 4; ++q) pv[q] = src4[tid + q * 256];
            if (tid < 64)
                pnb = use64 ? (int)((const long long*)ei)[NEDGE + (tile + GRID2P) * 64 + tid]
                            : ((const int*)ei)[NEDGE + (tile + GRID2P) * 64 + tid];
        }

        // epilogue: + h1[nbr] + h2[src] + bias; store g (fp16); accumulate stats
        #pragma unroll
        for (int mt = 0; mt < 2; ++mt)
            #pragma unroll
            for (int rr = 0; rr < 2; ++rr) {
                const int er = wr + mt * 16 + rr * 8 + g;
                const int e = e0 + er;
                const __half* h1 = g_h + (size_t)nbs[er] * 512 + chb;
                const __half* h2 = g_h + (size_t)(e / 12) * 512 + 256 + chb;
                __half* go = g_g + (size_t)e * 256 + chb;
                #pragma unroll
                for (int nt = 0; nt < 4; ++nt) {
                    int c = wc + nt * 8 + 2 * tg;
                    float2 p1 = __half22float2(*(const __half2*)(h1 + c));
                    float2 p2 = __half22float2(*(const __half2*)(h2 + c));
                    float v0 = acc[mt][nt][rr * 2]     + p1.x + p2.x + bs[c];
                    float v1 = acc[mt][nt][rr * 2 + 1] + p1.y + p2.y + bs[c + 1];
                    *(__half2*)(go + c) = __floats2half2_rn(v0, v1);
                    ssum[nt * 2]     += v0; ssq[nt * 2]     += v0 * v0;
                    ssum[nt * 2 + 1] += v1; ssq[nt * 2 + 1] += v1 * v1;
                }
            }
    }

    // reduce stats across lanes sharing the same columns (xor over g bits)
    #pragma unroll
    for (int q = 0; q < 8; ++q) {
        #pragma unroll
        for (int off = 4; off < 32; off <<= 1) {
            ssum[q] += __shfl_xor_sync(0xFFFFFFFFu, ssum[q], off);
            ssq[q]  += __shfl_xor_sync(0xFFFFFFFFu, ssq[q],  off);
        }
    }
    __syncthreads();
    if (lane < 4) {
        #pragma unroll
        for (int nt = 0; nt < 4; ++nt)
            #pragma unroll
            for (int j = 0; j < 2; ++j) {
                int sl = nt * 8 + 2 * lane + j;
                sred[w * 64 + sl]      = ssum[nt * 2 + j];
                sred[w * 64 + 32 + sl] = ssq[nt * 2 + j];
            }
    }
    __syncthreads();
    if (tid < 128) {
        int c = tid, strip = c >> 5, cl = c & 31;
        float s  = sred[strip * 64 + cl]      + sred[(strip + 4) * 64 + cl];
        float sq = sred[strip * 64 + 32 + cl] + sred[(strip + 4) * 64 + 32 + cl];
        float* dst = g_part1 + (size_t)(pair * 2 + half) * 256;
        dst[c] = s;
        dst[128 + c] = sq;
    }
}

// ---------------- k3: BN1 finalize (warp per channel) ----------------
__global__ void k3_bn1(const float* __restrict__ g1, const float* __restrict__ b1) {
    const int tid = threadIdx.x, lane = tid & 31;
    const int c = blockIdx.x * 8 + (tid >> 5);    // grid 32 x 8 warps = 256 channels
    const int half = c >> 7, cl = c & 127;
    float s = 0.0f, q = 0.0f;
    for (int pr = lane; pr < GRID2P; pr += 32) {
        const float* src = g_part1 + (size_t)(pr * 2 + half) * 256;
        s += src[cl];
        q += src[128 + cl];
    }
    #pragma unroll
    for (int off = 16; off > 0; off >>= 1) {
        s += __shfl_xor_sync(0xFFFFFFFFu, s, off);
        q += __shfl_xor_sync(0xFFFFFFFFu, q, off);
    }
    if (lane == 0) {
        float mean = s * (1.0f / (float)NEDGE);
        float var  = q * (1.0f / (float)NEDGE) - mean * mean;
        float rstd = rsqrtf(var + 1e-5f);
        float sc = g1[c] * rstd;
        g_bn1_scale[c] = sc;
        g_bn1_shift[c] = b1[c] - mean * sc;
    }
}

// ---------------- k4: per-node reduce + activations + BN2 partials ----------------
__global__ void __launch_bounds__(256)
k4_reduce() {
    __shared__ float red[8 * 128];
    const int tid = threadIdx.x, lane = tid & 31, wrp = tid >> 5;

    float scf[2][2], shf[2][2], scc[2][2], shc[2][2];
    #pragma unroll
    for (int j = 0; j < 2; ++j)
        #pragma unroll
        for (int q = 0; q < 2; ++q) {
            int c = 2 * lane + 64 * j + q;
            scf[j][q] = g_bn1_scale[c];       shf[j][q] = g_bn1_shift[c];
            scc[j][q] = g_bn1_scale[128 + c]; shc[j][q] = g_bn1_shift[128 + c];
        }
    float stm[2][2] = {{0, 0}, {0, 0}}, stq[2][2] = {{0, 0}, {0, 0}};
    const int base_i = blockIdx.x * 32 + wrp * 4;

    for (int nn = 0; nn < 4; ++nn) {
        int i = base_i + nn;
        if (i < N_NODES) {
            float s[2][2] = {{0, 0}, {0, 0}};
            const __half* grow = g_g + (size_t)i * 12 * 256;
            #pragma unroll
            for (int el = 0; el < 12; ++el) {
                #pragma unroll
                for (int j = 0; j < 2; ++j) {
                    int c = 2 * lane + 64 * j;
                    float2 gf = __half22float2(*(const __half2*)(grow + el * 256 + c));
                    float2 gc = __half22float2(*(const __half2*)(grow + el * 256 + 128 + c));
                    float f0 = gf.x * scf[j][0] + shf[j][0];
                    float f1 = gf.y * scf[j][1] + shf[j][1];
                    float c0 = gc.x * scc[j][0] + shc[j][0];
                    float c1 = gc.y * scc[j][1] + shc[j][1];
                    s[j][0] += sigmoidf_(f0) * softplusf_(c0);
                    s[j][1] += sigmoidf_(f1) * softplusf_(c1);
                }
            }
            #pragma unroll
            for (int j = 0; j < 2; ++j) {
                *(float2*)(g_s + (size_t)i * 128 + 2 * lane + 64 * j) =
                    make_float2(s[j][0], s[j][1]);
                stm[j][0] += s[j][0]; stq[j][0] += s[j][0] * s[j][0];
                stm[j][1] += s[j][1]; stq[j][1] += s[j][1] * s[j][1];
            }
        }
    }

    #pragma unroll
    for (int j = 0; j < 2; ++j)
        #pragma unroll
        for (int q = 0; q < 2; ++q)
            red[wrp * 128 + 2 * lane + 64 * j + q] = stm[j][q];
    __syncthreads();
    if (tid < 128) {
        float t = 0.0f;
        #pragma unroll
        for (int w = 0; w < 8; ++w) t += red[w * 128 + tid];
        g_part2[blockIdx.x * 256 + tid] = t;
    }
    __syncthreads();
    #pragma unroll
    for (int j = 0; j < 2; ++j)
        #pragma unroll
        for (int q = 0; q < 2; ++q)
            red[wrp * 128 + 2 * lane + 64 * j + q] = stq[j][q];
    __syncthreads();
    if (tid < 128) {
        float t = 0.0f;
        #pragma unroll
        for (int w = 0; w < 8; ++w) t += red[w * 128 + tid];
        g_part2[blockIdx.x * 256 + 128 + tid] = t;
    }
}

// ---------------- k5: BN2 finalize ----------------
__global__ void k5_bn2(const float* __restrict__ g2, const float* __restrict__ b2) {
    __shared__ float rs[256], rq[256];
    const int c = blockIdx.x, tid = threadIdx.x;
    float ps = 0.0f, pq = 0.0f;
    for (int bb = tid; bb < GRID4; bb += 256) {
        ps += g_part2[bb * 256 + c];
        pq += g_part2[bb * 256 + 128 + c];
    }
    rs[tid] = ps; rq[tid] = pq;
    __syncthreads();
    for (int off = 128; off > 0; off >>= 1) {
        if (tid < off) { rs[tid] += rs[tid + off]; rq[tid] += rq[tid + off]; }
        __syncthreads();
    }
    if (tid == 0) {
        float mean = rs[0] * (1.0f / (float)N_NODES);
        float var  = rq[0] * (1.0f / (float)N_NODES) - mean * mean;
        float rstd = rsqrtf(var + 1e-5f);
        float sc = g2[c] * rstd;
        g_bn2_scale[c] = sc;
        g_bn2_shift[c] = b2[c] - mean * sc;
    }
}

// ---------------- k6: out = softplus(x + BN2(s)) ----------------
__global__ void k6_final(const float* __restrict__ x, float* __restrict__ out) {
    const int total4 = N_NODES * 32;
    for (int i4 = blockIdx.x * blockDim.x + threadIdx.x; i4 < total4;
         i4 += gridDim.x * blockDim.x) {
        float4 xv = ((const float4*)x)[i4];
        float4 sv = ((const float4*)g_s)[i4];
        int cb = (i4 & 31) << 2;
        float4 o;
        o.x = softplusf_(xv.x + sv.x * g_bn2_scale[cb + 0] + g_bn2_shift[cb + 0]);
        o.y = softplusf_(xv.y + sv.y * g_bn2_scale[cb + 1] + g_bn2_shift[cb + 1]);
        o.z = softplusf_(xv.z + sv.z * g_bn2_scale[cb + 2] + g_bn2_shift[cb + 2]);
        o.w = softplusf_(xv.w + sv.w * g_bn2_scale[cb + 3] + g_bn2_shift[cb + 3]);
        ((float4*)out)[i4] = o;
    }
}

// ---------------- launch ----------------
extern "C" void kernel_launch(void* const* d_in, const int* in_sizes, int n_in,
                              void* d_out, int out_size) {
    const float* x   = (const float*)d_in[0];
    const void*  ei  = d_in[1];
    const float* ea  = (const float*)d_in[2];
    const float* W   = (const float*)d_in[3];
    const float* b   = (const float*)d_in[4];
    const float* b1g = (const float*)d_in[5];
    const float* b1b = (const float*)d_in[6];
    const float* b2g = (const float*)d_in[7];
    const float* b2b = (const float*)d_in[8];
    float* out = (float*)d_out;

    const int smem1 = K1_SMEM_FL * 4;   // 101,376 B -> 2 CTAs/SM
    const int smem2 = K2_SMEM_FL * 4;   //  55,040 B -> 2 CTAs/SM
    cudaFuncSetAttribute(k1_gemm, cudaFuncAttributeMaxDynamicSharedMemorySize, smem1);
    cudaFuncSetAttribute(k2_edge, cudaFuncAttributeMaxDynamicSharedMemorySize, smem2);

    k0_detect<<<1, 32>>>(ei);
    k1_gemm<<<dim3(NT1, 2, 2), 256, smem1>>>(x, W);
    k2_edge<<<2 * GRID2P, 256, smem2>>>(ea, ei, W, b);
    k3_bn1<<<32, 256>>>(b1g, b1b);
    k4_reduce<<<GRID4, 256>>>();
    k5_bn2<<<128, 256>>>(b2g, b2b);
    k6_final<<<592, 256>>>(x, out);
}